// round 5
// baseline (speedup 1.0000x reference)
#include <cuda_runtime.h>
#include <math.h>

// ---------------------------------------------------------------------------
// MS-SSIM loss. 10 channels 1024x1024 fp32, 5 levels.
// ONE persistent kernel: all 5 levels + combine, software grid barriers.
// Separable 11-tap gaussian, register sliding windows, f32x2 packed FMA,
// fused 2x2 avg-pool, offset-by-0.5 variance trick.
// ---------------------------------------------------------------------------

#define NCH 10
#define TX 32     // output tile width
#define TY 54     // output tile height
#define NBLK 444  // 148 SMs x 3 resident CTAs

__device__ constexpr float GW[11] = {
    0.00102842f, 0.00759877f, 0.03600077f, 0.10936076f, 0.21300535f,
    0.26601172f,
    0.21300535f, 0.10936076f, 0.03600077f, 0.00759877f, 0.00102842f};

__device__ float g_sim_acc[50];   // [level][channel]
__device__ float g_cs_acc[50];
__device__ int g_bar_count;       // zero-init
__device__ int g_bar_gen;         // monotonic

#define SCR_TOTAL 3481600
__device__ __align__(16) float g_scr_p[SCR_TOTAL];
__device__ __align__(16) float g_scr_t[SCR_TOTAL];

// per-level geometry (H, tile grid, scratch offsets)
__constant__ int c_H[5]      = {1024, 512, 256, 128, 64};
__constant__ int c_gx[5]     = {32, 16, 8, 4, 2};
__constant__ int c_gy[5]     = {19, 10, 5, 3, 1};
__constant__ int c_inoff[5]  = {0, 0, 2621440, 3276800, 3440640};
__constant__ int c_outoff[5] = {0, 2621440, 3276800, 3440640, 0};

// ---- f32x2 packed math helpers (Blackwell) --------------------------------
typedef unsigned long long ull;

__device__ __forceinline__ ull pk2(float a, float b) {
    ull r; asm("mov.b64 %0, {%1, %2};" : "=l"(r) : "f"(a), "f"(b)); return r;
}
__device__ __forceinline__ void upk2(ull v, float& a, float& b) {
    asm("mov.b64 {%0, %1}, %2;" : "=f"(a), "=f"(b) : "l"(v));
}
#define FMA2(d, a, b, c) \
    asm("fma.rn.f32x2 %0, %1, %2, %3;" : "=l"(d) : "l"(a), "l"(b), "l"(c))
#define MUL2(d, a, b) \
    asm("mul.rn.f32x2 %0, %1, %2;" : "=l"(d) : "l"(a), "l"(b))

// ---- software grid barrier (all NBLK CTAs resident -> deadlock-free) ------
__device__ __forceinline__ void grid_barrier()
{
    __syncthreads();
    if (threadIdx.x == 0) {
        __threadfence();
        int gen = *((volatile int*)&g_bar_gen);
        if (atomicAdd(&g_bar_count, 1) == (int)gridDim.x - 1) {
            g_bar_count = 0;
            __threadfence();
            atomicAdd(&g_bar_gen, 1);
        } else {
            while (*((volatile int*)&g_bar_gen) == gen) { __nanosleep(128); }
        }
        __threadfence();
    }
    __syncthreads();
}

// ---------------------------------------------------------------------------
// One SSIM tile (+ fused pool). Offset space: inputs already have 0.5
// subtracted at level 0 (sub=0.5); scratch holds offset data (sub=0).
// ---------------------------------------------------------------------------
__device__ __forceinline__ void ssim_tile(
    const float* __restrict__ P, const float* __restrict__ T,
    int H, int level, int out_off, int do_pool, float sub,
    int ch, int bx, int by)
{
    const int W = H;
    const int OH = H - 10;
    const int t = threadIdx.x;

    __shared__ float2 hs01[66][33];
    __shared__ float2 hs23[66][33];
    __shared__ float  hs4 [66][33];
    __shared__ float rs[8], rc[8];

    const float* Pc = P + (size_t)ch * H * W;
    const float* Tc = T + (size_t)ch * H * W;

    ull W2[11];
#pragma unroll
    for (int i = 0; i < 11; i++) W2[i] = pk2(GW[i], GW[i]);

    // ---------------- Stage A: horizontal pass + fused pool ----------------
    {
        const int r  = t >> 2;          // 0..63
        const int c0 = (t & 3) * 8;     // 0,8,16,24
        const int gy = by + r;
        const bool rowok = gy < H;
        const float* rowP = Pc + (size_t)gy * W + bx + c0;
        const float* rowT = Tc + (size_t)gy * W + bx + c0;

        ull s01[8], s23[8];
        float s4[8];
        float plP[4], plT[4];
#pragma unroll
        for (int j = 0; j < 8; j++) { s01[j] = 0ULL; s23[j] = 0ULL; s4[j] = 0.f; }

#pragma unroll
        for (int chk = 0; chk < 5; chk++) {
            float4 pv4 = make_float4(0.f, 0.f, 0.f, 0.f);
            float4 tv4 = make_float4(0.f, 0.f, 0.f, 0.f);
            int gx = bx + c0 + chk * 4;
            if (rowok && gx < W) {
                pv4 = *(const float4*)(rowP + chk * 4);
                tv4 = *(const float4*)(rowT + chk * 4);
            }
            pv4.x -= sub; pv4.y -= sub; pv4.z -= sub; pv4.w -= sub;
            tv4.x -= sub; tv4.y -= sub; tv4.z -= sub; tv4.w -= sub;

            if (chk < 2) {
                plP[chk * 2 + 0] = pv4.x + pv4.y;
                plP[chk * 2 + 1] = pv4.z + pv4.w;
                plT[chk * 2 + 0] = tv4.x + tv4.y;
                plT[chk * 2 + 1] = tv4.z + tv4.w;
            }

            const float pa[4] = {pv4.x, pv4.y, pv4.z, pv4.w};
            const float ta[4] = {tv4.x, tv4.y, tv4.z, tv4.w};
#pragma unroll
            for (int q = 0; q < 4; q++) {
                const int k = chk * 4 + q;
                if (k < 18) {
                    float pv = pa[q], tv = ta[q];
                    ull ptp = pk2(pv, tv);
                    ull sqp; MUL2(sqp, ptp, ptp);
                    float ptv = pv * tv;
#pragma unroll
                    for (int j = 0; j < 8; j++) {
                        const int i = k - j;
                        if (i >= 0 && i <= 10) {
                            FMA2(s01[j], W2[i], ptp, s01[j]);
                            FMA2(s23[j], W2[i], sqp, s23[j]);
                            s4[j] = fmaf(GW[i], ptv, s4[j]);
                        }
                    }
                }
            }

            // fused 2x2 pool (rows r<->r+1 are lanes +-4 in same warp)
            if (chk == 1 && do_pool) {
                float vp[4], vt[4];
#pragma unroll
                for (int q = 0; q < 4; q++) {
                    vp[q] = plP[q] + __shfl_down_sync(0xffffffffu, plP[q], 4);
                    vt[q] = plT[q] + __shfl_down_sync(0xffffffffu, plT[q], 4);
                }
                if (((r & 1) == 0) && (gy + 1 < H)) {
                    const int Ho = H >> 1;
                    size_t o = (size_t)ch * Ho * Ho + (size_t)(gy >> 1) * Ho
                               + ((bx + c0) >> 1);
                    *(float4*)(g_scr_p + out_off + o) =
                        make_float4(0.25f * vp[0], 0.25f * vp[1],
                                    0.25f * vp[2], 0.25f * vp[3]);
                    *(float4*)(g_scr_t + out_off + o) =
                        make_float4(0.25f * vt[0], 0.25f * vt[1],
                                    0.25f * vt[2], 0.25f * vt[3]);
                }
            }
        }
#pragma unroll
        for (int j = 0; j < 8; j++) {
            float a, b;
            upk2(s01[j], a, b); hs01[r][c0 + j] = make_float2(a, b);
            upk2(s23[j], a, b); hs23[r][c0 + j] = make_float2(a, b);
            hs4[r][c0 + j] = s4[j];
        }
    }
    __syncthreads();

    // ---------------- Stage B: vertical pass + SSIM ----------------
    const float C1v = 0.01f * 0.01f;
    const float C2v = 0.03f * 0.03f;
    float lsim = 0.f, lcs = 0.f;
    {
        const int tx = t & 31;
        const int g  = t >> 5;
        const int r0 = g * 7;
        const int cnt = (54 - r0) < 7 ? (54 - r0) : 7;
        const int ox = bx + tx;

        ull a01[7], a23[7];
        float a4[7];
#pragma unroll
        for (int j = 0; j < 7; j++) { a01[j] = 0ULL; a23[j] = 0ULL; a4[j] = 0.f; }

#pragma unroll
        for (int k = 0; k < 17; k++) {
            float2 h01 = hs01[r0 + k][tx];
            float2 h23 = hs23[r0 + k][tx];
            float  h4  = hs4 [r0 + k][tx];
            ull h01p = pk2(h01.x, h01.y);
            ull h23p = pk2(h23.x, h23.y);
#pragma unroll
            for (int j = 0; j < 7; j++) {
                const int i = k - j;
                if (i >= 0 && i <= 10) {
                    FMA2(a01[j], W2[i], h01p, a01[j]);
                    FMA2(a23[j], W2[i], h23p, a23[j]);
                    a4[j] = fmaf(GW[i], h4, a4[j]);
                }
            }
        }

#pragma unroll
        for (int j = 0; j < 7; j++) {
            int oy = by + r0 + j;
            if (j < cnt && oy < OH && ox < OH) {
                float m1o, m2o, spp, stt;
                upk2(a01[j], m1o, m2o);
                upk2(a23[j], spp, stt);
                float spt = a4[j];
                float s1  = spp - m1o * m1o;
                float s2  = stt - m2o * m2o;
                float s12 = spt - m1o * m2o;
                float m1 = m1o + 0.5f, m2 = m2o + 0.5f;
                float m1s = m1 * m1, m2s = m2 * m2, m12 = m1 * m2;
                float v1 = 2.f * s12 + C2v;
                float v2 = s1 + s2 + C2v;
                float cs  = __fdividef(v1, v2);
                float sim = cs * __fdividef(2.f * m12 + C1v, m1s + m2s + C1v);
                lcs  += cs;
                lsim += sim;
            }
        }
    }

    // block reduce + atomic accumulate
#pragma unroll
    for (int o = 16; o > 0; o >>= 1) {
        lsim += __shfl_down_sync(0xffffffff, lsim, o);
        lcs  += __shfl_down_sync(0xffffffff, lcs, o);
    }
    if ((t & 31) == 0) { rs[t >> 5] = lsim; rc[t >> 5] = lcs; }
    __syncthreads();
    if (t == 0) {
        float ss = 0.f, cc = 0.f;
#pragma unroll
        for (int i = 0; i < 8; i++) { ss += rs[i]; cc += rc[i]; }
        atomicAdd(&g_sim_acc[level * NCH + ch], ss);
        atomicAdd(&g_cs_acc[level * NCH + ch], cc);
    }
    __syncthreads();   // protect smem reuse by next tile
}

// ---------------------------------------------------------------------------
__global__ __launch_bounds__(256, 3)
void mssim_all_kernel(const float* __restrict__ P, const float* __restrict__ T,
                      float* __restrict__ out)
{
#pragma unroll 1
    for (int l = 0; l < 5; l++) {
        const int gx = c_gx[l], gy = c_gy[l];
        const int per_ch = gx * gy;
        const int tiles = per_ch * NCH;
        const int H = c_H[l];
        const float* Pl = (l == 0) ? P : (const float*)(g_scr_p + c_inoff[l]);
        const float* Tl = (l == 0) ? T : (const float*)(g_scr_t + c_inoff[l]);
        const int out_off = c_outoff[l];
        const int do_pool = (l < 4) ? 1 : 0;
        const float sub = (l == 0) ? 0.5f : 0.0f;

#pragma unroll 1
        for (int w = blockIdx.x; w < tiles; w += gridDim.x) {
            int ch  = w / per_ch;
            int rem = w - ch * per_ch;
            int tyI = rem / gx;
            int txI = rem - tyI * gx;
            ssim_tile(Pl, Tl, H, l, out_off, do_pool, sub,
                      ch, txI * TX, tyI * TY);
        }
        grid_barrier();
    }

    // combine (block 0, thread 0)
    if (blockIdx.x == 0 && threadIdx.x == 0) {
        const double w[5]   = {0.0448, 0.2856, 0.3001, 0.2363, 0.1333};
        const double cnt[5] = {1014.0 * 1014.0, 502.0 * 502.0, 246.0 * 246.0,
                               118.0 * 118.0, 54.0 * 54.0};
        double total = 0.0;
        for (int c = 0; c < NCH; c++) {
            double ms4 = (double)g_sim_acc[4 * NCH + c] / cnt[4];
            double p2  = pow(ms4, w[4]);
            double pc  = 1.0;
            for (int l = 0; l < 4; l++) {
                double mc = (double)g_cs_acc[l * NCH + c] / cnt[l];
                pc *= pow(mc, w[l]) * p2;
            }
            total += pc;
        }
        out[0] = (float)(1.0 - total);
        for (int i = 0; i < 50; i++) { g_sim_acc[i] = 0.f; g_cs_acc[i] = 0.f; }
    }
}

extern "C" void kernel_launch(void* const* d_in, const int* in_sizes, int n_in,
                              void* d_out, int out_size)
{
    const float* P = (const float*)d_in[0];
    const float* T = (const float*)d_in[1];
    float* out = (float*)d_out;
    mssim_all_kernel<<<NBLK, 256>>>(P, T, out);
}

// round 6
// speedup vs baseline: 2.2203x; 2.2203x over previous
#include <cuda_runtime.h>
#include <math.h>

// ---------------------------------------------------------------------------
// MS-SSIM loss. 10 channels 1024x1024 fp32, 5 levels.
// Hybrid: standalone L0 kernel (bulk work), persistent kernel for L1-4 +
// combine with software grid barriers. Separable 11-tap gaussian, register
// sliding windows, f32x2 packed FMA, fused 2x2 pool, offset-0.5 trick.
// ---------------------------------------------------------------------------

#define NCH 10
#define TX 32
#define TY 54
#define NBLK 444  // 148 SMs x 3 resident CTAs

__device__ constexpr float GW[11] = {
    0.00102842f, 0.00759877f, 0.03600077f, 0.10936076f, 0.21300535f,
    0.26601172f,
    0.21300535f, 0.10936076f, 0.03600077f, 0.00759877f, 0.00102842f};

__device__ float g_sim_acc[50];   // [level][channel]
__device__ float g_cs_acc[50];
__device__ int g_bar_count;
__device__ int g_bar_gen;

#define SCR_TOTAL 3481600
__device__ __align__(16) float g_scr_p[SCR_TOTAL];
__device__ __align__(16) float g_scr_t[SCR_TOTAL];

// levels 1..4 geometry
__constant__ int c_H[5]      = {1024, 512, 256, 128, 64};
__constant__ int c_gx[5]     = {32, 16, 8, 4, 2};
__constant__ int c_gy[5]     = {19, 10, 5, 3, 1};
__constant__ int c_inoff[5]  = {0, 0, 2621440, 3276800, 3440640};
__constant__ int c_outoff[5] = {0, 2621440, 3276800, 3440640, 0};

// ---- f32x2 packed math helpers --------------------------------------------
typedef unsigned long long ull;

__device__ __forceinline__ ull pk2(float a, float b) {
    ull r; asm("mov.b64 %0, {%1, %2};" : "=l"(r) : "f"(a), "f"(b)); return r;
}
__device__ __forceinline__ void upk2(ull v, float& a, float& b) {
    asm("mov.b64 {%0, %1}, %2;" : "=f"(a), "=f"(b) : "l"(v));
}
#define FMA2(d, a, b, c) \
    asm("fma.rn.f32x2 %0, %1, %2, %3;" : "=l"(d) : "l"(a), "l"(b), "l"(c))
#define MUL2(d, a, b) \
    asm("mul.rn.f32x2 %0, %1, %2;" : "=l"(d) : "l"(a), "l"(b))

__device__ __forceinline__ void grid_barrier()
{
    __syncthreads();
    if (threadIdx.x == 0) {
        __threadfence();
        int gen = *((volatile int*)&g_bar_gen);
        if (atomicAdd(&g_bar_count, 1) == (int)gridDim.x - 1) {
            g_bar_count = 0;
            __threadfence();
            atomicAdd(&g_bar_gen, 1);
        } else {
            while (*((volatile int*)&g_bar_gen) == gen) { __nanosleep(128); }
        }
        __threadfence();
    }
    __syncthreads();
}

// ---------------------------------------------------------------------------
// One SSIM tile (+ fused pool). Offset space (x - 0.5).
// ---------------------------------------------------------------------------
__device__ __forceinline__ void ssim_tile(
    const float* __restrict__ P, const float* __restrict__ T,
    int H, int level, int out_off, int do_pool, float sub,
    int ch, int bx, int by)
{
    const int W = H;
    const int OH = H - 10;
    const int t = threadIdx.x;

    __shared__ float2 hs01[66][33];
    __shared__ float2 hs23[66][33];
    __shared__ float  hs4 [66][33];
    __shared__ float rs[8], rc[8];

    const float* Pc = P + (size_t)ch * H * W;
    const float* Tc = T + (size_t)ch * H * W;

    ull W2[11];
#pragma unroll
    for (int i = 0; i < 11; i++) W2[i] = pk2(GW[i], GW[i]);

    // ---------------- Stage A: horizontal pass + fused pool ----------------
    {
        const int r  = t >> 2;
        const int c0 = (t & 3) * 8;
        const int gy = by + r;
        const bool rowok = gy < H;
        const float* rowP = Pc + (size_t)gy * W + bx + c0;
        const float* rowT = Tc + (size_t)gy * W + bx + c0;

        ull s01[8], s23[8];
        float s4[8];
        float plP[4], plT[4];
#pragma unroll
        for (int j = 0; j < 8; j++) { s01[j] = 0ULL; s23[j] = 0ULL; s4[j] = 0.f; }

#pragma unroll
        for (int chk = 0; chk < 5; chk++) {
            float4 pv4 = make_float4(0.f, 0.f, 0.f, 0.f);
            float4 tv4 = make_float4(0.f, 0.f, 0.f, 0.f);
            int gx = bx + c0 + chk * 4;
            if (rowok && gx < W) {
                pv4 = *(const float4*)(rowP + chk * 4);
                tv4 = *(const float4*)(rowT + chk * 4);
            }
            pv4.x -= sub; pv4.y -= sub; pv4.z -= sub; pv4.w -= sub;
            tv4.x -= sub; tv4.y -= sub; tv4.z -= sub; tv4.w -= sub;

            if (chk < 2) {
                plP[chk * 2 + 0] = pv4.x + pv4.y;
                plP[chk * 2 + 1] = pv4.z + pv4.w;
                plT[chk * 2 + 0] = tv4.x + tv4.y;
                plT[chk * 2 + 1] = tv4.z + tv4.w;
            }

            const float pa[4] = {pv4.x, pv4.y, pv4.z, pv4.w};
            const float ta[4] = {tv4.x, tv4.y, tv4.z, tv4.w};
#pragma unroll
            for (int q = 0; q < 4; q++) {
                const int k = chk * 4 + q;
                if (k < 18) {
                    float pv = pa[q], tv = ta[q];
                    ull ptp = pk2(pv, tv);
                    ull sqp; MUL2(sqp, ptp, ptp);
                    float ptv = pv * tv;
#pragma unroll
                    for (int j = 0; j < 8; j++) {
                        const int i = k - j;
                        if (i >= 0 && i <= 10) {
                            FMA2(s01[j], W2[i], ptp, s01[j]);
                            FMA2(s23[j], W2[i], sqp, s23[j]);
                            s4[j] = fmaf(GW[i], ptv, s4[j]);
                        }
                    }
                }
            }

            if (chk == 1 && do_pool) {
                float vp[4], vt[4];
#pragma unroll
                for (int q = 0; q < 4; q++) {
                    vp[q] = plP[q] + __shfl_down_sync(0xffffffffu, plP[q], 4);
                    vt[q] = plT[q] + __shfl_down_sync(0xffffffffu, plT[q], 4);
                }
                if (((r & 1) == 0) && (gy + 1 < H)) {
                    const int Ho = H >> 1;
                    size_t o = (size_t)ch * Ho * Ho + (size_t)(gy >> 1) * Ho
                               + ((bx + c0) >> 1);
                    *(float4*)(g_scr_p + out_off + o) =
                        make_float4(0.25f * vp[0], 0.25f * vp[1],
                                    0.25f * vp[2], 0.25f * vp[3]);
                    *(float4*)(g_scr_t + out_off + o) =
                        make_float4(0.25f * vt[0], 0.25f * vt[1],
                                    0.25f * vt[2], 0.25f * vt[3]);
                }
            }
        }
#pragma unroll
        for (int j = 0; j < 8; j++) {
            float a, b;
            upk2(s01[j], a, b); hs01[r][c0 + j] = make_float2(a, b);
            upk2(s23[j], a, b); hs23[r][c0 + j] = make_float2(a, b);
            hs4[r][c0 + j] = s4[j];
        }
    }
    __syncthreads();

    // ---------------- Stage B: vertical pass + SSIM ----------------
    const float C1v = 0.01f * 0.01f;
    const float C2v = 0.03f * 0.03f;
    float lsim = 0.f, lcs = 0.f;
    {
        const int tx = t & 31;
        const int g  = t >> 5;
        const int r0 = g * 7;
        const int cnt = (54 - r0) < 7 ? (54 - r0) : 7;
        const int ox = bx + tx;

        ull a01[7], a23[7];
        float a4[7];
#pragma unroll
        for (int j = 0; j < 7; j++) { a01[j] = 0ULL; a23[j] = 0ULL; a4[j] = 0.f; }

#pragma unroll
        for (int k = 0; k < 17; k++) {
            float2 h01 = hs01[r0 + k][tx];
            float2 h23 = hs23[r0 + k][tx];
            float  h4  = hs4 [r0 + k][tx];
            ull h01p = pk2(h01.x, h01.y);
            ull h23p = pk2(h23.x, h23.y);
#pragma unroll
            for (int j = 0; j < 7; j++) {
                const int i = k - j;
                if (i >= 0 && i <= 10) {
                    FMA2(a01[j], W2[i], h01p, a01[j]);
                    FMA2(a23[j], W2[i], h23p, a23[j]);
                    a4[j] = fmaf(GW[i], h4, a4[j]);
                }
            }
        }

#pragma unroll
        for (int j = 0; j < 7; j++) {
            int oy = by + r0 + j;
            if (j < cnt && oy < OH && ox < OH) {
                float m1o, m2o, spp, stt;
                upk2(a01[j], m1o, m2o);
                upk2(a23[j], spp, stt);
                float spt = a4[j];
                float s1  = spp - m1o * m1o;
                float s2  = stt - m2o * m2o;
                float s12 = spt - m1o * m2o;
                float m1 = m1o + 0.5f, m2 = m2o + 0.5f;
                float m1s = m1 * m1, m2s = m2 * m2, m12 = m1 * m2;
                float v1 = 2.f * s12 + C2v;
                float v2 = s1 + s2 + C2v;
                float cs  = __fdividef(v1, v2);
                float sim = cs * __fdividef(2.f * m12 + C1v, m1s + m2s + C1v);
                lcs  += cs;
                lsim += sim;
            }
        }
    }

#pragma unroll
    for (int o = 16; o > 0; o >>= 1) {
        lsim += __shfl_down_sync(0xffffffff, lsim, o);
        lcs  += __shfl_down_sync(0xffffffff, lcs, o);
    }
    if ((t & 31) == 0) { rs[t >> 5] = lsim; rc[t >> 5] = lcs; }
    __syncthreads();
    if (t == 0) {
        float ss = 0.f, cc = 0.f;
#pragma unroll
        for (int i = 0; i < 8; i++) { ss += rs[i]; cc += rc[i]; }
        atomicAdd(&g_sim_acc[level * NCH + ch], ss);
        atomicAdd(&g_cs_acc[level * NCH + ch], cc);
    }
    __syncthreads();
}

// ---------------------------------------------------------------------------
// L0: standalone, one tile per CTA (6080 CTAs). Subtract 0.5, pool to scratch.
// ---------------------------------------------------------------------------
__global__ __launch_bounds__(256, 3)
void ssim_l0_kernel(const float* __restrict__ P, const float* __restrict__ T)
{
    ssim_tile(P, T, 1024, 0, 0, 1, 0.5f,
              blockIdx.z, blockIdx.x * TX, blockIdx.y * TY);
}

// ---------------------------------------------------------------------------
// Persistent kernel: levels 1..4 with grid barriers, then parallel combine.
// ---------------------------------------------------------------------------
__global__ __launch_bounds__(256, 3)
void ssim_rest_kernel(float* __restrict__ out)
{
#pragma unroll 1
    for (int l = 1; l < 5; l++) {
        const int gx = c_gx[l], gyn = c_gy[l];
        const int per_ch = gx * gyn;
        const int tiles = per_ch * NCH;
        const int H = c_H[l];
        const float* Pl = (const float*)(g_scr_p + c_inoff[l]);
        const float* Tl = (const float*)(g_scr_t + c_inoff[l]);
        const int out_off = c_outoff[l];
        const int do_pool = (l < 4) ? 1 : 0;

#pragma unroll 1
        for (int w = blockIdx.x; w < tiles; w += gridDim.x) {
            int ch  = w / per_ch;
            int rem = w - ch * per_ch;
            int tyI = rem / gx;
            int txI = rem - tyI * gx;
            ssim_tile(Pl, Tl, H, l, out_off, do_pool, 0.0f,
                      ch, txI * TX, tyI * TY);
        }
        grid_barrier();
    }

    // parallel combine: thread c (<10) handles category c
    if (blockIdx.x == 0) {
        __shared__ double part[NCH];
        const int t = threadIdx.x;
        if (t < NCH) {
            const double w[5]   = {0.0448, 0.2856, 0.3001, 0.2363, 0.1333};
            const double cnt[5] = {1014.0 * 1014.0, 502.0 * 502.0,
                                   246.0 * 246.0, 118.0 * 118.0, 54.0 * 54.0};
            double ms4 = (double)g_sim_acc[4 * NCH + t] / cnt[4];
            double p2  = pow(ms4, w[4]);
            double pc  = 1.0;
            for (int l = 0; l < 4; l++) {
                double mc = (double)g_cs_acc[l * NCH + t] / cnt[l];
                pc *= pow(mc, w[l]) * p2;
            }
            part[t] = pc;
        }
        __syncthreads();
        if (t == 0) {
            double total = 0.0;
            for (int c = 0; c < NCH; c++) total += part[c];
            out[0] = (float)(1.0 - total);
        }
        // reset accumulators for next replay
        if (t < 50) { g_sim_acc[t] = 0.f; g_cs_acc[t] = 0.f; }
    }
}

extern "C" void kernel_launch(void* const* d_in, const int* in_sizes, int n_in,
                              void* d_out, int out_size)
{
    const float* P = (const float*)d_in[0];
    const float* T = (const float*)d_in[1];
    float* out = (float*)d_out;

    dim3 grid0(32, 19, NCH);   // ceil(1014/32), ceil(1014/54), channels
    ssim_l0_kernel<<<grid0, 256>>>(P, T);
    ssim_rest_kernel<<<NBLK, 256>>>(out);
}

// round 8
// speedup vs baseline: 2.2906x; 1.0316x over previous
#include <cuda_runtime.h>
#include <math.h>

// ---------------------------------------------------------------------------
// MS-SSIM loss. 10 channels 1024x1024 fp32, 5 levels.
// Hybrid: standalone L0 kernel + persistent kernel (L1-4 + combine).
// ssim_tile templated on H (all index math folds); SMEM workspace declared
// ONCE at kernel scope and passed by pointer so template instantiations share
// it (4 separate instances deadlocked the grid barrier in R7: 174KB static
// smem -> 1 CTA/SM -> 444-CTA barrier never satisfied).
// ---------------------------------------------------------------------------

#define NCH 10
#define TX 32
#define TY 54
#define NBLK 444  // 148 SMs x 3 resident CTAs

__device__ constexpr float GW[11] = {
    0.00102842f, 0.00759877f, 0.03600077f, 0.10936076f, 0.21300535f,
    0.26601172f,
    0.21300535f, 0.10936076f, 0.03600077f, 0.00759877f, 0.00102842f};

__device__ float g_sim_acc[50];   // [level][channel]
__device__ float g_cs_acc[50];
__device__ int g_bar_count;
__device__ int g_bar_gen;

#define SCR_TOTAL 3481600
__device__ __align__(16) float g_scr_p[SCR_TOTAL];
__device__ __align__(16) float g_scr_t[SCR_TOTAL];

// shared workspace: 43,624 bytes -> 3 CTAs/SM
struct SmemWS {
    float2 hs01[66][33];
    float2 hs23[66][33];
    float  hs4 [66][33];
    float  rs[8], rc[8];
};

// ---- f32x2 packed math helpers --------------------------------------------
typedef unsigned long long ull;

__device__ __forceinline__ ull pk2(float a, float b) {
    ull r; asm("mov.b64 %0, {%1, %2};" : "=l"(r) : "f"(a), "f"(b)); return r;
}
__device__ __forceinline__ void upk2(ull v, float& a, float& b) {
    asm("mov.b64 {%0, %1}, %2;" : "=f"(a), "=f"(b) : "l"(v));
}
#define FMA2(d, a, b, c) \
    asm("fma.rn.f32x2 %0, %1, %2, %3;" : "=l"(d) : "l"(a), "l"(b), "l"(c))
#define MUL2(d, a, b) \
    asm("mul.rn.f32x2 %0, %1, %2;" : "=l"(d) : "l"(a), "l"(b))

__device__ __forceinline__ void grid_barrier()
{
    __syncthreads();
    if (threadIdx.x == 0) {
        __threadfence();
        int gen = *((volatile int*)&g_bar_gen);
        if (atomicAdd(&g_bar_count, 1) == (int)gridDim.x - 1) {
            g_bar_count = 0;
            __threadfence();
            atomicAdd(&g_bar_gen, 1);
        } else {
            while (*((volatile int*)&g_bar_gen) == gen) { __nanosleep(128); }
        }
        __threadfence();
    }
    __syncthreads();
}

// ---------------------------------------------------------------------------
// One SSIM tile (+ fused pool). H compile-time: all addressing folds.
// Offset space (x - 0.5): SUB subtracts at load (level 0); scratch already
// holds offset data for deeper levels.
// ---------------------------------------------------------------------------
template <int H, bool DO_POOL, bool SUB>
__device__ __forceinline__ void ssim_tile(
    SmemWS* ws,
    const float* __restrict__ P, const float* __restrict__ T,
    int level, int out_off, int ch, int bx, int by)
{
    constexpr int W = H;
    constexpr int OH = H - 10;
    const int t = threadIdx.x;

    const float* Pc = P + (size_t)ch * (H * W);
    const float* Tc = T + (size_t)ch * (H * W);

    ull W2[11];
#pragma unroll
    for (int i = 0; i < 11; i++) W2[i] = pk2(GW[i], GW[i]);

    // ---------------- Stage A: horizontal pass + fused pool ----------------
    {
        const int r  = t >> 2;
        const int c0 = (t & 3) * 8;
        const int gy = by + r;
        const bool rowok = gy < H;
        const float* rowP = Pc + (size_t)gy * W + bx + c0;
        const float* rowT = Tc + (size_t)gy * W + bx + c0;

        ull s01[8], s23[8];
        float s4[8];
        float plP[4], plT[4];
#pragma unroll
        for (int j = 0; j < 8; j++) { s01[j] = 0ULL; s23[j] = 0ULL; s4[j] = 0.f; }

#pragma unroll
        for (int chk = 0; chk < 5; chk++) {
            float4 pv4 = make_float4(0.f, 0.f, 0.f, 0.f);
            float4 tv4 = make_float4(0.f, 0.f, 0.f, 0.f);
            int gx = bx + c0 + chk * 4;
            if (rowok && gx < W) {
                pv4 = *(const float4*)(rowP + chk * 4);
                tv4 = *(const float4*)(rowT + chk * 4);
            }
            if (SUB) {
                pv4.x -= 0.5f; pv4.y -= 0.5f; pv4.z -= 0.5f; pv4.w -= 0.5f;
                tv4.x -= 0.5f; tv4.y -= 0.5f; tv4.z -= 0.5f; tv4.w -= 0.5f;
            }

            if (DO_POOL && chk < 2) {
                plP[chk * 2 + 0] = pv4.x + pv4.y;
                plP[chk * 2 + 1] = pv4.z + pv4.w;
                plT[chk * 2 + 0] = tv4.x + tv4.y;
                plT[chk * 2 + 1] = tv4.z + tv4.w;
            }

            const float pa[4] = {pv4.x, pv4.y, pv4.z, pv4.w};
            const float ta[4] = {tv4.x, tv4.y, tv4.z, tv4.w};
#pragma unroll
            for (int q = 0; q < 4; q++) {
                const int k = chk * 4 + q;
                if (k < 18) {
                    float pv = pa[q], tv = ta[q];
                    ull ptp = pk2(pv, tv);
                    ull sqp; MUL2(sqp, ptp, ptp);
                    float ptv = pv * tv;
#pragma unroll
                    for (int j = 0; j < 8; j++) {
                        const int i = k - j;
                        if (i >= 0 && i <= 10) {
                            FMA2(s01[j], W2[i], ptp, s01[j]);
                            FMA2(s23[j], W2[i], sqp, s23[j]);
                            s4[j] = fmaf(GW[i], ptv, s4[j]);
                        }
                    }
                }
            }

            if (DO_POOL && chk == 1) {
                float vp[4], vt[4];
#pragma unroll
                for (int q = 0; q < 4; q++) {
                    vp[q] = plP[q] + __shfl_down_sync(0xffffffffu, plP[q], 4);
                    vt[q] = plT[q] + __shfl_down_sync(0xffffffffu, plT[q], 4);
                }
                if (((r & 1) == 0) && (gy + 1 < H)) {
                    constexpr int Ho = H >> 1;
                    size_t o = (size_t)ch * (Ho * Ho) + (size_t)(gy >> 1) * Ho
                               + ((bx + c0) >> 1);
                    *(float4*)(g_scr_p + out_off + o) =
                        make_float4(0.25f * vp[0], 0.25f * vp[1],
                                    0.25f * vp[2], 0.25f * vp[3]);
                    *(float4*)(g_scr_t + out_off + o) =
                        make_float4(0.25f * vt[0], 0.25f * vt[1],
                                    0.25f * vt[2], 0.25f * vt[3]);
                }
            }
        }
#pragma unroll
        for (int j = 0; j < 8; j++) {
            float a, b;
            upk2(s01[j], a, b); ws->hs01[r][c0 + j] = make_float2(a, b);
            upk2(s23[j], a, b); ws->hs23[r][c0 + j] = make_float2(a, b);
            ws->hs4[r][c0 + j] = s4[j];
        }
    }
    __syncthreads();

    // ---------------- Stage B: vertical pass + SSIM ----------------
    const float C1v = 0.01f * 0.01f;
    const float C2v = 0.03f * 0.03f;
    float lsim = 0.f, lcs = 0.f;
    {
        const int tx = t & 31;
        const int g  = t >> 5;
        const int r0 = g * 7;
        const int cnt = (54 - r0) < 7 ? (54 - r0) : 7;
        const int ox = bx + tx;

        ull a01[7], a23[7];
        float a4[7];
#pragma unroll
        for (int j = 0; j < 7; j++) { a01[j] = 0ULL; a23[j] = 0ULL; a4[j] = 0.f; }

#pragma unroll
        for (int k = 0; k < 17; k++) {
            float2 h01 = ws->hs01[r0 + k][tx];
            float2 h23 = ws->hs23[r0 + k][tx];
            float  h4  = ws->hs4 [r0 + k][tx];
            ull h01p = pk2(h01.x, h01.y);
            ull h23p = pk2(h23.x, h23.y);
#pragma unroll
            for (int j = 0; j < 7; j++) {
                const int i = k - j;
                if (i >= 0 && i <= 10) {
                    FMA2(a01[j], W2[i], h01p, a01[j]);
                    FMA2(a23[j], W2[i], h23p, a23[j]);
                    a4[j] = fmaf(GW[i], h4, a4[j]);
                }
            }
        }

#pragma unroll
        for (int j = 0; j < 7; j++) {
            int oy = by + r0 + j;
            if (j < cnt && oy < OH && ox < OH) {
                float m1o, m2o, spp, stt;
                upk2(a01[j], m1o, m2o);
                upk2(a23[j], spp, stt);
                float spt = a4[j];
                float s1  = spp - m1o * m1o;
                float s2  = stt - m2o * m2o;
                float s12 = spt - m1o * m2o;
                float m1 = m1o + 0.5f, m2 = m2o + 0.5f;
                float m1s = m1 * m1, m2s = m2 * m2, m12 = m1 * m2;
                float v1 = 2.f * s12 + C2v;
                float v2 = s1 + s2 + C2v;
                float cs  = __fdividef(v1, v2);
                float sim = cs * __fdividef(2.f * m12 + C1v, m1s + m2s + C1v);
                lcs  += cs;
                lsim += sim;
            }
        }
    }

#pragma unroll
    for (int o = 16; o > 0; o >>= 1) {
        lsim += __shfl_down_sync(0xffffffff, lsim, o);
        lcs  += __shfl_down_sync(0xffffffff, lcs, o);
    }
    if ((t & 31) == 0) { ws->rs[t >> 5] = lsim; ws->rc[t >> 5] = lcs; }
    __syncthreads();
    if (t == 0) {
        float ss = 0.f, cc = 0.f;
#pragma unroll
        for (int i = 0; i < 8; i++) { ss += ws->rs[i]; cc += ws->rc[i]; }
        atomicAdd(&g_sim_acc[level * NCH + ch], ss);
        atomicAdd(&g_cs_acc[level * NCH + ch], cc);
    }
    __syncthreads();
}

// ---------------------------------------------------------------------------
// L0: standalone, one tile per CTA (6080 CTAs).
// ---------------------------------------------------------------------------
__global__ __launch_bounds__(256, 3)
void ssim_l0_kernel(const float* __restrict__ P, const float* __restrict__ T)
{
    __shared__ SmemWS ws;
    ssim_tile<1024, true, true>(&ws, P, T, 0, 0,
                                blockIdx.z, blockIdx.x * TX, blockIdx.y * TY);
}

// ---------------------------------------------------------------------------
// Persistent kernel: levels 1..4 with grid barriers, then parallel combine.
// ---------------------------------------------------------------------------
template <int H, bool DO_POOL>
__device__ __forceinline__ void run_level(SmemWS* ws, int level,
                                          int in_off, int out_off)
{
    constexpr int gx  = (H - 10 + TX - 1) / TX;
    constexpr int gyn = (H - 10 + TY - 1) / TY;
    constexpr int per_ch = gx * gyn;
    constexpr int tiles = per_ch * NCH;
    const float* Pl = (const float*)(g_scr_p + in_off);
    const float* Tl = (const float*)(g_scr_t + in_off);

#pragma unroll 1
    for (int w = blockIdx.x; w < tiles; w += gridDim.x) {
        int ch  = w / per_ch;
        int rem = w - ch * per_ch;
        int tyI = rem / gx;
        int txI = rem - tyI * gx;
        ssim_tile<H, DO_POOL, false>(ws, Pl, Tl, level, out_off,
                                     ch, txI * TX, tyI * TY);
    }
}

__global__ __launch_bounds__(256, 3)
void ssim_rest_kernel(float* __restrict__ out)
{
    __shared__ SmemWS ws;   // single instance shared by all instantiations

    run_level<512, true >(&ws, 1, 0,       2621440);
    grid_barrier();
    run_level<256, true >(&ws, 2, 2621440, 3276800);
    grid_barrier();
    run_level<128, true >(&ws, 3, 3276800, 3440640);
    grid_barrier();
    run_level<64,  false>(&ws, 4, 3440640, 0);
    grid_barrier();

    // parallel combine: thread c (<10) handles category c
    if (blockIdx.x == 0) {
        __shared__ double part[NCH];
        const int t = threadIdx.x;
        if (t < NCH) {
            const double w[5]   = {0.0448, 0.2856, 0.3001, 0.2363, 0.1333};
            const double cnt[5] = {1014.0 * 1014.0, 502.0 * 502.0,
                                   246.0 * 246.0, 118.0 * 118.0, 54.0 * 54.0};
            double ms4 = (double)g_sim_acc[4 * NCH + t] / cnt[4];
            double p2  = pow(ms4, w[4]);
            double pc  = 1.0;
            for (int l = 0; l < 4; l++) {
                double mc = (double)g_cs_acc[l * NCH + t] / cnt[l];
                pc *= pow(mc, w[l]) * p2;
            }
            part[t] = pc;
        }
        __syncthreads();
        if (t == 0) {
            double total = 0.0;
            for (int c = 0; c < NCH; c++) total += part[c];
            out[0] = (float)(1.0 - total);
        }
        if (t < 50) { g_sim_acc[t] = 0.f; g_cs_acc[t] = 0.f; }
    }
}

extern "C" void kernel_launch(void* const* d_in, const int* in_sizes, int n_in,
                              void* d_out, int out_size)
{
    const float* P = (const float*)d_in[0];
    const float* T = (const float*)d_in[1];
    float* out = (float*)d_out;

    dim3 grid0(32, 19, NCH);
    ssim_l0_kernel<<<grid0, 256>>>(P, T);
    ssim_rest_kernel<<<NBLK, 256>>>(out);
}

// round 9
// speedup vs baseline: 2.7350x; 1.1940x over previous
#include <cuda_runtime.h>
#include <math.h>

// ---------------------------------------------------------------------------
// MS-SSIM loss. 10 channels 1024x1024 fp32, 5 levels.
// L0 and L1: standalone kernels (embarrassingly parallel).
// L2-L4 + combine: one persistent kernel with software grid barriers.
// Combine is pure fp32 (log2f/exp2f) - no fp64 softfloat pow.
// ---------------------------------------------------------------------------

#define NCH 10
#define TX 32
#define TY 54
#define NBLK2 400  // rest kernel: exactly L2's tile count, <= 444 resident

__device__ constexpr float GW[11] = {
    0.00102842f, 0.00759877f, 0.03600077f, 0.10936076f, 0.21300535f,
    0.26601172f,
    0.21300535f, 0.10936076f, 0.03600077f, 0.00759877f, 0.00102842f};

__device__ float g_sim_acc[50];   // [level][channel]
__device__ float g_cs_acc[50];
__device__ int g_bar_count;
__device__ int g_bar_gen;

#define SCR_TOTAL 3481600
__device__ __align__(16) float g_scr_p[SCR_TOTAL];
__device__ __align__(16) float g_scr_t[SCR_TOTAL];

// scratch offsets: L1 input at 0 (written by L0), L2 in at 2621440, etc.
#define OFF_L1 0
#define OFF_L2 2621440
#define OFF_L3 3276800
#define OFF_L4 3440640

// shared workspace: 43,624 bytes -> 3 CTAs/SM
struct SmemWS {
    float2 hs01[66][33];
    float2 hs23[66][33];
    float  hs4 [66][33];
    float  rs[8], rc[8];
};

// ---- f32x2 packed math helpers --------------------------------------------
typedef unsigned long long ull;

__device__ __forceinline__ ull pk2(float a, float b) {
    ull r; asm("mov.b64 %0, {%1, %2};" : "=l"(r) : "f"(a), "f"(b)); return r;
}
__device__ __forceinline__ void upk2(ull v, float& a, float& b) {
    asm("mov.b64 {%0, %1}, %2;" : "=f"(a), "=f"(b) : "l"(v));
}
#define FMA2(d, a, b, c) \
    asm("fma.rn.f32x2 %0, %1, %2, %3;" : "=l"(d) : "l"(a), "l"(b), "l"(c))
#define MUL2(d, a, b) \
    asm("mul.rn.f32x2 %0, %1, %2;" : "=l"(d) : "l"(a), "l"(b))

__device__ __forceinline__ void grid_barrier()
{
    __syncthreads();
    if (threadIdx.x == 0) {
        __threadfence();
        int gen = *((volatile int*)&g_bar_gen);
        if (atomicAdd(&g_bar_count, 1) == (int)gridDim.x - 1) {
            g_bar_count = 0;
            __threadfence();
            atomicAdd(&g_bar_gen, 1);
        } else {
            while (*((volatile int*)&g_bar_gen) == gen) { __nanosleep(128); }
        }
        __threadfence();
    }
    __syncthreads();
}

// ---------------------------------------------------------------------------
// One SSIM tile (+ fused pool). H compile-time. Offset space (x - 0.5).
// ---------------------------------------------------------------------------
template <int H, bool DO_POOL, bool SUB>
__device__ __forceinline__ void ssim_tile(
    SmemWS* ws,
    const float* __restrict__ P, const float* __restrict__ T,
    int level, int out_off, int ch, int bx, int by)
{
    constexpr int W = H;
    constexpr int OH = H - 10;
    const int t = threadIdx.x;

    const float* Pc = P + (size_t)ch * (H * W);
    const float* Tc = T + (size_t)ch * (H * W);

    ull W2[11];
#pragma unroll
    for (int i = 0; i < 11; i++) W2[i] = pk2(GW[i], GW[i]);

    // ---------------- Stage A: horizontal pass + fused pool ----------------
    {
        const int r  = t >> 2;
        const int c0 = (t & 3) * 8;
        const int gy = by + r;
        const bool rowok = gy < H;
        const float* rowP = Pc + (size_t)gy * W + bx + c0;
        const float* rowT = Tc + (size_t)gy * W + bx + c0;

        ull s01[8], s23[8];
        float s4[8];
        float plP[4], plT[4];
#pragma unroll
        for (int j = 0; j < 8; j++) { s01[j] = 0ULL; s23[j] = 0ULL; s4[j] = 0.f; }

#pragma unroll
        for (int chk = 0; chk < 5; chk++) {
            float4 pv4 = make_float4(0.f, 0.f, 0.f, 0.f);
            float4 tv4 = make_float4(0.f, 0.f, 0.f, 0.f);
            int gx = bx + c0 + chk * 4;
            if (rowok && gx < W) {
                pv4 = *(const float4*)(rowP + chk * 4);
                tv4 = *(const float4*)(rowT + chk * 4);
            }
            if (SUB) {
                pv4.x -= 0.5f; pv4.y -= 0.5f; pv4.z -= 0.5f; pv4.w -= 0.5f;
                tv4.x -= 0.5f; tv4.y -= 0.5f; tv4.z -= 0.5f; tv4.w -= 0.5f;
            }

            if (DO_POOL && chk < 2) {
                plP[chk * 2 + 0] = pv4.x + pv4.y;
                plP[chk * 2 + 1] = pv4.z + pv4.w;
                plT[chk * 2 + 0] = tv4.x + tv4.y;
                plT[chk * 2 + 1] = tv4.z + tv4.w;
            }

            const float pa[4] = {pv4.x, pv4.y, pv4.z, pv4.w};
            const float ta[4] = {tv4.x, tv4.y, tv4.z, tv4.w};
#pragma unroll
            for (int q = 0; q < 4; q++) {
                const int k = chk * 4 + q;
                if (k < 18) {
                    float pv = pa[q], tv = ta[q];
                    ull ptp = pk2(pv, tv);
                    ull sqp; MUL2(sqp, ptp, ptp);
                    float ptv = pv * tv;
#pragma unroll
                    for (int j = 0; j < 8; j++) {
                        const int i = k - j;
                        if (i >= 0 && i <= 10) {
                            FMA2(s01[j], W2[i], ptp, s01[j]);
                            FMA2(s23[j], W2[i], sqp, s23[j]);
                            s4[j] = fmaf(GW[i], ptv, s4[j]);
                        }
                    }
                }
            }

            if (DO_POOL && chk == 1) {
                float vp[4], vt[4];
#pragma unroll
                for (int q = 0; q < 4; q++) {
                    vp[q] = plP[q] + __shfl_down_sync(0xffffffffu, plP[q], 4);
                    vt[q] = plT[q] + __shfl_down_sync(0xffffffffu, plT[q], 4);
                }
                if (((r & 1) == 0) && (gy + 1 < H)) {
                    constexpr int Ho = H >> 1;
                    size_t o = (size_t)ch * (Ho * Ho) + (size_t)(gy >> 1) * Ho
                               + ((bx + c0) >> 1);
                    *(float4*)(g_scr_p + out_off + o) =
                        make_float4(0.25f * vp[0], 0.25f * vp[1],
                                    0.25f * vp[2], 0.25f * vp[3]);
                    *(float4*)(g_scr_t + out_off + o) =
                        make_float4(0.25f * vt[0], 0.25f * vt[1],
                                    0.25f * vt[2], 0.25f * vt[3]);
                }
            }
        }
#pragma unroll
        for (int j = 0; j < 8; j++) {
            float a, b;
            upk2(s01[j], a, b); ws->hs01[r][c0 + j] = make_float2(a, b);
            upk2(s23[j], a, b); ws->hs23[r][c0 + j] = make_float2(a, b);
            ws->hs4[r][c0 + j] = s4[j];
        }
    }
    __syncthreads();

    // ---------------- Stage B: vertical pass + SSIM ----------------
    const float C1v = 0.01f * 0.01f;
    const float C2v = 0.03f * 0.03f;
    float lsim = 0.f, lcs = 0.f;
    {
        const int tx = t & 31;
        const int g  = t >> 5;
        const int r0 = g * 7;
        const int cnt = (54 - r0) < 7 ? (54 - r0) : 7;
        const int ox = bx + tx;

        ull a01[7], a23[7];
        float a4[7];
#pragma unroll
        for (int j = 0; j < 7; j++) { a01[j] = 0ULL; a23[j] = 0ULL; a4[j] = 0.f; }

#pragma unroll
        for (int k = 0; k < 17; k++) {
            float2 h01 = ws->hs01[r0 + k][tx];
            float2 h23 = ws->hs23[r0 + k][tx];
            float  h4  = ws->hs4 [r0 + k][tx];
            ull h01p = pk2(h01.x, h01.y);
            ull h23p = pk2(h23.x, h23.y);
#pragma unroll
            for (int j = 0; j < 7; j++) {
                const int i = k - j;
                if (i >= 0 && i <= 10) {
                    FMA2(a01[j], W2[i], h01p, a01[j]);
                    FMA2(a23[j], W2[i], h23p, a23[j]);
                    a4[j] = fmaf(GW[i], h4, a4[j]);
                }
            }
        }

#pragma unroll
        for (int j = 0; j < 7; j++) {
            int oy = by + r0 + j;
            if (j < cnt && oy < OH && ox < OH) {
                float m1o, m2o, spp, stt;
                upk2(a01[j], m1o, m2o);
                upk2(a23[j], spp, stt);
                float spt = a4[j];
                float s1  = spp - m1o * m1o;
                float s2  = stt - m2o * m2o;
                float s12 = spt - m1o * m2o;
                float m1 = m1o + 0.5f, m2 = m2o + 0.5f;
                float m1s = m1 * m1, m2s = m2 * m2, m12 = m1 * m2;
                float v1 = 2.f * s12 + C2v;
                float v2 = s1 + s2 + C2v;
                float cs  = __fdividef(v1, v2);
                float sim = cs * __fdividef(2.f * m12 + C1v, m1s + m2s + C1v);
                lcs  += cs;
                lsim += sim;
            }
        }
    }

#pragma unroll
    for (int o = 16; o > 0; o >>= 1) {
        lsim += __shfl_down_sync(0xffffffff, lsim, o);
        lcs  += __shfl_down_sync(0xffffffff, lcs, o);
    }
    if ((t & 31) == 0) { ws->rs[t >> 5] = lsim; ws->rc[t >> 5] = lcs; }
    __syncthreads();
    if (t == 0) {
        float ss = 0.f, cc = 0.f;
#pragma unroll
        for (int i = 0; i < 8; i++) { ss += ws->rs[i]; cc += ws->rc[i]; }
        atomicAdd(&g_sim_acc[level * NCH + ch], ss);
        atomicAdd(&g_cs_acc[level * NCH + ch], cc);
    }
    __syncthreads();
}

// ---------------------------------------------------------------------------
// L0 / L1: standalone, one tile per CTA.
// ---------------------------------------------------------------------------
__global__ __launch_bounds__(256, 3)
void ssim_l0_kernel(const float* __restrict__ P, const float* __restrict__ T)
{
    __shared__ SmemWS ws;
    ssim_tile<1024, true, true>(&ws, P, T, 0, OFF_L1,
                                blockIdx.z, blockIdx.x * TX, blockIdx.y * TY);
}

__global__ __launch_bounds__(256, 3)
void ssim_l1_kernel()
{
    __shared__ SmemWS ws;
    ssim_tile<512, true, false>(&ws, g_scr_p + OFF_L1, g_scr_t + OFF_L1,
                                1, OFF_L2,
                                blockIdx.z, blockIdx.x * TX, blockIdx.y * TY);
}

// ---------------------------------------------------------------------------
// Persistent kernel: levels 2..4 with grid barriers, then fp32 combine.
// ---------------------------------------------------------------------------
template <int H, bool DO_POOL>
__device__ __forceinline__ void run_level(SmemWS* ws, int level,
                                          int in_off, int out_off)
{
    constexpr int gx  = (H - 10 + TX - 1) / TX;
    constexpr int gyn = (H - 10 + TY - 1) / TY;
    constexpr int per_ch = gx * gyn;
    constexpr int tiles = per_ch * NCH;
    const float* Pl = (const float*)(g_scr_p + in_off);
    const float* Tl = (const float*)(g_scr_t + in_off);

#pragma unroll 1
    for (int w = blockIdx.x; w < tiles; w += gridDim.x) {
        int ch  = w / per_ch;
        int rem = w - ch * per_ch;
        int tyI = rem / gx;
        int txI = rem - tyI * gx;
        ssim_tile<H, DO_POOL, false>(ws, Pl, Tl, level, out_off,
                                     ch, txI * TX, tyI * TY);
    }
}

__global__ __launch_bounds__(256, 3)
void ssim_rest_kernel(float* __restrict__ out)
{
    __shared__ SmemWS ws;   // single instance shared by all instantiations

    run_level<256, true >(&ws, 2, OFF_L2, OFF_L3);
    grid_barrier();
    run_level<128, true >(&ws, 3, OFF_L3, OFF_L4);
    grid_barrier();
    run_level<64,  false>(&ws, 4, OFF_L4, 0);
    grid_barrier();

    // fp32 combine: thread c (<10) handles category c; no fp64 anywhere.
    if (blockIdx.x == 0) {
        __shared__ float part[NCH];
        const int t = threadIdx.x;
        if (t < NCH) {
            const float w[5]    = {0.0448f, 0.2856f, 0.3001f, 0.2363f, 0.1333f};
            const float icnt[5] = {1.f / (1014.f * 1014.f), 1.f / (502.f * 502.f),
                                   1.f / (246.f * 246.f),  1.f / (118.f * 118.f),
                                   1.f / (54.f * 54.f)};
            float ms4 = g_sim_acc[4 * NCH + t] * icnt[4];
            float e = 4.0f * w[4] * log2f(ms4);
            for (int l = 0; l < 4; l++) {
                float mc = g_cs_acc[l * NCH + t] * icnt[l];
                e += w[l] * log2f(mc);
            }
            part[t] = exp2f(e);
        }
        __syncthreads();
        if (t == 0) {
            float total = 0.f;
            for (int c = 0; c < NCH; c++) total += part[c];
            out[0] = 1.0f - total;
        }
        if (t < 50) { g_sim_acc[t] = 0.f; g_cs_acc[t] = 0.f; }
    }
}

extern "C" void kernel_launch(void* const* d_in, const int* in_sizes, int n_in,
                              void* d_out, int out_size)
{
    const float* P = (const float*)d_in[0];
    const float* T = (const float*)d_in[1];
    float* out = (float*)d_out;

    dim3 grid0(32, 19, NCH);   // L0: 1024 -> OH 1014
    ssim_l0_kernel<<<grid0, 256>>>(P, T);
    dim3 grid1(16, 10, NCH);   // L1: 512 -> OH 502
    ssim_l1_kernel<<<grid1, 256>>>();
    ssim_rest_kernel<<<NBLK2, 256>>>(out);
}

// round 10
// speedup vs baseline: 2.8853x; 1.0549x over previous
#include <cuda_runtime.h>
#include <math.h>

// ---------------------------------------------------------------------------
// MS-SSIM loss. 10 channels 1024x1024 fp32, 5 levels.
// L0, L1: standalone kernels. L2-L4 + combine: persistent kernel w/ barriers.
// 4-conv formulation: SSIM only needs sigma1^2+sigma2^2, so convolve
// u = p^2+t^2 as ONE field. Quantities pack into two f32x2 accumulators:
// (p,t) and (p^2+t^2, p*t) -> pure FMA2 inner loops, 44 MAC-cyc/output.
// ---------------------------------------------------------------------------

#define NCH 10
#define TX 32
#define TY 54
#define NBLK2 400

__device__ constexpr float GW[11] = {
    0.00102842f, 0.00759877f, 0.03600077f, 0.10936076f, 0.21300535f,
    0.26601172f,
    0.21300535f, 0.10936076f, 0.03600077f, 0.00759877f, 0.00102842f};

__device__ float g_sim_acc[50];   // [level][channel]
__device__ float g_cs_acc[50];
__device__ int g_bar_count;
__device__ int g_bar_gen;

#define SCR_TOTAL 3481600
__device__ __align__(16) float g_scr_p[SCR_TOTAL];
__device__ __align__(16) float g_scr_t[SCR_TOTAL];

#define OFF_L1 0
#define OFF_L2 2621440
#define OFF_L3 3276800
#define OFF_L4 3440640

// shared workspace: ~34.9 KB
struct SmemWS {
    float2 hs01[66][33];   // (mu_p, mu_t) horizontal partials
    float2 hs2 [66][33];   // (E[p^2+t^2], E[pt]) horizontal partials
    float  rs[8], rc[8];
};

// ---- f32x2 packed math helpers --------------------------------------------
typedef unsigned long long ull;

__device__ __forceinline__ ull pk2(float a, float b) {
    ull r; asm("mov.b64 %0, {%1, %2};" : "=l"(r) : "f"(a), "f"(b)); return r;
}
__device__ __forceinline__ void upk2(ull v, float& a, float& b) {
    asm("mov.b64 {%0, %1}, %2;" : "=f"(a), "=f"(b) : "l"(v));
}
#define FMA2(d, a, b, c) \
    asm("fma.rn.f32x2 %0, %1, %2, %3;" : "=l"(d) : "l"(a), "l"(b), "l"(c))

__device__ __forceinline__ void grid_barrier()
{
    __syncthreads();
    if (threadIdx.x == 0) {
        __threadfence();
        int gen = *((volatile int*)&g_bar_gen);
        if (atomicAdd(&g_bar_count, 1) == (int)gridDim.x - 1) {
            g_bar_count = 0;
            __threadfence();
            atomicAdd(&g_bar_gen, 1);
        } else {
            while (*((volatile int*)&g_bar_gen) == gen) { __nanosleep(128); }
        }
        __threadfence();
    }
    __syncthreads();
}

// ---------------------------------------------------------------------------
// One SSIM tile (+ fused pool). H compile-time. Offset space (x - 0.5).
// ---------------------------------------------------------------------------
template <int H, bool DO_POOL, bool SUB>
__device__ __forceinline__ void ssim_tile(
    SmemWS* ws,
    const float* __restrict__ P, const float* __restrict__ T,
    int level, int out_off, int ch, int bx, int by)
{
    constexpr int W = H;
    constexpr int OH = H - 10;
    const int t = threadIdx.x;

    const float* Pc = P + (size_t)ch * (H * W);
    const float* Tc = T + (size_t)ch * (H * W);

    ull W2[11];
#pragma unroll
    for (int i = 0; i < 11; i++) W2[i] = pk2(GW[i], GW[i]);

    // ---------------- Stage A: horizontal pass + fused pool ----------------
    {
        const int r  = t >> 2;
        const int c0 = (t & 3) * 8;
        const int gy = by + r;
        const bool rowok = gy < H;
        const float* rowP = Pc + (size_t)gy * W + bx + c0;
        const float* rowT = Tc + (size_t)gy * W + bx + c0;

        ull s01[8], s2[8];
        float plP[4], plT[4];
#pragma unroll
        for (int j = 0; j < 8; j++) { s01[j] = 0ULL; s2[j] = 0ULL; }

#pragma unroll
        for (int chk = 0; chk < 5; chk++) {
            float4 pv4 = make_float4(0.f, 0.f, 0.f, 0.f);
            float4 tv4 = make_float4(0.f, 0.f, 0.f, 0.f);
            int gx = bx + c0 + chk * 4;
            if (rowok && gx < W) {
                pv4 = *(const float4*)(rowP + chk * 4);
                tv4 = *(const float4*)(rowT + chk * 4);
            }
            if (SUB) {
                pv4.x -= 0.5f; pv4.y -= 0.5f; pv4.z -= 0.5f; pv4.w -= 0.5f;
                tv4.x -= 0.5f; tv4.y -= 0.5f; tv4.z -= 0.5f; tv4.w -= 0.5f;
            }

            if (DO_POOL && chk < 2) {
                plP[chk * 2 + 0] = pv4.x + pv4.y;
                plP[chk * 2 + 1] = pv4.z + pv4.w;
                plT[chk * 2 + 0] = tv4.x + tv4.y;
                plT[chk * 2 + 1] = tv4.z + tv4.w;
            }

            const float pa[4] = {pv4.x, pv4.y, pv4.z, pv4.w};
            const float ta[4] = {tv4.x, tv4.y, tv4.z, tv4.w};
#pragma unroll
            for (int q = 0; q < 4; q++) {
                const int k = chk * 4 + q;
                if (k < 18) {
                    float pv = pa[q], tv = ta[q];
                    ull ptp = pk2(pv, tv);
                    float ssv = fmaf(pv, pv, tv * tv);   // p^2 + t^2
                    float ptv = pv * tv;
                    ull ssp = pk2(ssv, ptv);
#pragma unroll
                    for (int j = 0; j < 8; j++) {
                        const int i = k - j;
                        if (i >= 0 && i <= 10) {
                            FMA2(s01[j], W2[i], ptp, s01[j]);
                            FMA2(s2[j],  W2[i], ssp, s2[j]);
                        }
                    }
                }
            }

            if (DO_POOL && chk == 1) {
                float vp[4], vt[4];
#pragma unroll
                for (int q = 0; q < 4; q++) {
                    vp[q] = plP[q] + __shfl_down_sync(0xffffffffu, plP[q], 4);
                    vt[q] = plT[q] + __shfl_down_sync(0xffffffffu, plT[q], 4);
                }
                if (((r & 1) == 0) && (gy + 1 < H)) {
                    constexpr int Ho = H >> 1;
                    size_t o = (size_t)ch * (Ho * Ho) + (size_t)(gy >> 1) * Ho
                               + ((bx + c0) >> 1);
                    *(float4*)(g_scr_p + out_off + o) =
                        make_float4(0.25f * vp[0], 0.25f * vp[1],
                                    0.25f * vp[2], 0.25f * vp[3]);
                    *(float4*)(g_scr_t + out_off + o) =
                        make_float4(0.25f * vt[0], 0.25f * vt[1],
                                    0.25f * vt[2], 0.25f * vt[3]);
                }
            }
        }
#pragma unroll
        for (int j = 0; j < 8; j++) {
            float a, b;
            upk2(s01[j], a, b); ws->hs01[r][c0 + j] = make_float2(a, b);
            upk2(s2[j],  a, b); ws->hs2 [r][c0 + j] = make_float2(a, b);
        }
    }
    __syncthreads();

    // ---------------- Stage B: vertical pass + SSIM ----------------
    const float C1v = 0.01f * 0.01f;
    const float C2v = 0.03f * 0.03f;
    float lsim = 0.f, lcs = 0.f;
    {
        const int tx = t & 31;
        const int g  = t >> 5;
        const int r0 = g * 7;
        const int cnt = (54 - r0) < 7 ? (54 - r0) : 7;
        const int ox = bx + tx;

        ull a01[7], a2[7];
#pragma unroll
        for (int j = 0; j < 7; j++) { a01[j] = 0ULL; a2[j] = 0ULL; }

#pragma unroll
        for (int k = 0; k < 17; k++) {
            float2 h01 = ws->hs01[r0 + k][tx];
            float2 h2  = ws->hs2 [r0 + k][tx];
            ull h01p = pk2(h01.x, h01.y);
            ull h2p  = pk2(h2.x,  h2.y);
#pragma unroll
            for (int j = 0; j < 7; j++) {
                const int i = k - j;
                if (i >= 0 && i <= 10) {
                    FMA2(a01[j], W2[i], h01p, a01[j]);
                    FMA2(a2[j],  W2[i], h2p,  a2[j]);
                }
            }
        }

#pragma unroll
        for (int j = 0; j < 7; j++) {
            int oy = by + r0 + j;
            if (j < cnt && oy < OH && ox < OH) {
                float m1o, m2o, ssq, spt;
                upk2(a01[j], m1o, m2o);
                upk2(a2[j],  ssq, spt);
                float s12 = spt - m1o * m2o;
                float v2  = ssq - m1o * m1o - m2o * m2o + C2v;
                float m1 = m1o + 0.5f, m2 = m2o + 0.5f;
                float m1s = m1 * m1, m2s = m2 * m2, m12 = m1 * m2;
                float v1 = 2.f * s12 + C2v;
                float cs  = __fdividef(v1, v2);
                float sim = cs * __fdividef(2.f * m12 + C1v, m1s + m2s + C1v);
                lcs  += cs;
                lsim += sim;
            }
        }
    }

#pragma unroll
    for (int o = 16; o > 0; o >>= 1) {
        lsim += __shfl_down_sync(0xffffffff, lsim, o);
        lcs  += __shfl_down_sync(0xffffffff, lcs, o);
    }
    if ((t & 31) == 0) { ws->rs[t >> 5] = lsim; ws->rc[t >> 5] = lcs; }
    __syncthreads();
    if (t == 0) {
        float ss = 0.f, cc = 0.f;
#pragma unroll
        for (int i = 0; i < 8; i++) { ss += ws->rs[i]; cc += ws->rc[i]; }
        atomicAdd(&g_sim_acc[level * NCH + ch], ss);
        atomicAdd(&g_cs_acc[level * NCH + ch], cc);
    }
    __syncthreads();
}

// ---------------------------------------------------------------------------
// L0 / L1: standalone, one tile per CTA.
// ---------------------------------------------------------------------------
__global__ __launch_bounds__(256, 3)
void ssim_l0_kernel(const float* __restrict__ P, const float* __restrict__ T)
{
    __shared__ SmemWS ws;
    ssim_tile<1024, true, true>(&ws, P, T, 0, OFF_L1,
                                blockIdx.z, blockIdx.x * TX, blockIdx.y * TY);
}

__global__ __launch_bounds__(256, 3)
void ssim_l1_kernel()
{
    __shared__ SmemWS ws;
    ssim_tile<512, true, false>(&ws, g_scr_p + OFF_L1, g_scr_t + OFF_L1,
                                1, OFF_L2,
                                blockIdx.z, blockIdx.x * TX, blockIdx.y * TY);
}

// ---------------------------------------------------------------------------
// Persistent kernel: levels 2..4 with grid barriers, then fp32 combine.
// ---------------------------------------------------------------------------
template <int H, bool DO_POOL>
__device__ __forceinline__ void run_level(SmemWS* ws, int level,
                                          int in_off, int out_off)
{
    constexpr int gx  = (H - 10 + TX - 1) / TX;
    constexpr int gyn = (H - 10 + TY - 1) / TY;
    constexpr int per_ch = gx * gyn;
    constexpr int tiles = per_ch * NCH;
    const float* Pl = (const float*)(g_scr_p + in_off);
    const float* Tl = (const float*)(g_scr_t + in_off);

#pragma unroll 1
    for (int w = blockIdx.x; w < tiles; w += gridDim.x) {
        int ch  = w / per_ch;
        int rem = w - ch * per_ch;
        int tyI = rem / gx;
        int txI = rem - tyI * gx;
        ssim_tile<H, DO_POOL, false>(ws, Pl, Tl, level, out_off,
                                     ch, txI * TX, tyI * TY);
    }
}

__global__ __launch_bounds__(256, 3)
void ssim_rest_kernel(float* __restrict__ out)
{
    __shared__ SmemWS ws;   // single instance shared by all instantiations

    run_level<256, true >(&ws, 2, OFF_L2, OFF_L3);
    grid_barrier();
    run_level<128, true >(&ws, 3, OFF_L3, OFF_L4);
    grid_barrier();
    run_level<64,  false>(&ws, 4, OFF_L4, 0);
    grid_barrier();

    // fp32 combine: thread c (<10) handles category c.
    if (blockIdx.x == 0) {
        __shared__ float part[NCH];
        const int t = threadIdx.x;
        if (t < NCH) {
            const float w[5]    = {0.0448f, 0.2856f, 0.3001f, 0.2363f, 0.1333f};
            const float icnt[5] = {1.f / (1014.f * 1014.f), 1.f / (502.f * 502.f),
                                   1.f / (246.f * 246.f),  1.f / (118.f * 118.f),
                                   1.f / (54.f * 54.f)};
            float ms4 = g_sim_acc[4 * NCH + t] * icnt[4];
            float e = 4.0f * w[4] * log2f(ms4);
            for (int l = 0; l < 4; l++) {
                float mc = g_cs_acc[l * NCH + t] * icnt[l];
                e += w[l] * log2f(mc);
            }
            part[t] = exp2f(e);
        }
        __syncthreads();
        if (t == 0) {
            float total = 0.f;
            for (int c = 0; c < NCH; c++) total += part[c];
            out[0] = 1.0f - total;
        }
        if (t < 50) { g_sim_acc[t] = 0.f; g_cs_acc[t] = 0.f; }
    }
}

extern "C" void kernel_launch(void* const* d_in, const int* in_sizes, int n_in,
                              void* d_out, int out_size)
{
    const float* P = (const float*)d_in[0];
    const float* T = (const float*)d_in[1];
    float* out = (float*)d_out;

    dim3 grid0(32, 19, NCH);   // L0: 1024 -> OH 1014
    ssim_l0_kernel<<<grid0, 256>>>(P, T);
    dim3 grid1(16, 10, NCH);   // L1: 512 -> OH 502
    ssim_l1_kernel<<<grid1, 256>>>();
    ssim_rest_kernel<<<NBLK2, 256>>>(out);
}

// round 11
// speedup vs baseline: 2.9614x; 1.0264x over previous
#include <cuda_runtime.h>
#include <math.h>

// ---------------------------------------------------------------------------
// MS-SSIM loss. 10 channels 1024x1024 fp32, 5 levels.
// L0, L1: standalone kernels. L2-L4 + combine: persistent kernel w/ barriers.
// 4-conv formulation; horizontal partials stored as ONE ulonglong2 per pixel
// (two packed f32x2 accumulators) with additive bank swizzle -> conflict-free
// STS.128 / LDS.128, half the smem instructions.
// ---------------------------------------------------------------------------

#define NCH 10
#define TX 32
#define TY 54
#define NBLK2 400

__device__ constexpr float GW[11] = {
    0.00102842f, 0.00759877f, 0.03600077f, 0.10936076f, 0.21300535f,
    0.26601172f,
    0.21300535f, 0.10936076f, 0.03600077f, 0.00759877f, 0.00102842f};

__device__ float g_sim_acc[50];   // [level][channel]
__device__ float g_cs_acc[50];
__device__ int g_bar_count;
__device__ int g_bar_gen;

#define SCR_TOTAL 3481600
__device__ __align__(16) float g_scr_p[SCR_TOTAL];
__device__ __align__(16) float g_scr_t[SCR_TOTAL];

#define OFF_L1 0
#define OFF_L2 2621440
#define OFF_L3 3276800
#define OFF_L4 3440640

// shared workspace: 66*32*16 + 64 = ~33.9 KB -> 3 CTAs/SM (reg-limited)
struct SmemWS {
    ulonglong2 hs[66][32];   // (s01, s2) packed pairs, bank-swizzled columns
    float rs[8], rc[8];
};

// swizzled column for logical (col, row):
//   col' = (col & 24) | (((col&7) + ((col>>3)&3) + 4*(row&1)) & 7)
// store side: per-warp phase covers all 8 bank-groups; load side: bijective
// per 8-lane group -> both directions conflict-free.
__device__ __forceinline__ int swz(int col, int row) {
    return (col & 24) | (((col & 7) + ((col >> 3) & 3) + ((row & 1) << 2)) & 7);
}

// ---- f32x2 packed math helpers --------------------------------------------
typedef unsigned long long ull;

__device__ __forceinline__ ull pk2(float a, float b) {
    ull r; asm("mov.b64 %0, {%1, %2};" : "=l"(r) : "f"(a), "f"(b)); return r;
}
__device__ __forceinline__ void upk2(ull v, float& a, float& b) {
    asm("mov.b64 {%0, %1}, %2;" : "=f"(a), "=f"(b) : "l"(v));
}
#define FMA2(d, a, b, c) \
    asm("fma.rn.f32x2 %0, %1, %2, %3;" : "=l"(d) : "l"(a), "l"(b), "l"(c))

__device__ __forceinline__ void grid_barrier()
{
    __syncthreads();
    if (threadIdx.x == 0) {
        __threadfence();
        int gen = *((volatile int*)&g_bar_gen);
        if (atomicAdd(&g_bar_count, 1) == (int)gridDim.x - 1) {
            g_bar_count = 0;
            __threadfence();
            atomicAdd(&g_bar_gen, 1);
        } else {
            while (*((volatile int*)&g_bar_gen) == gen) { __nanosleep(128); }
        }
        __threadfence();
    }
    __syncthreads();
}

// ---------------------------------------------------------------------------
// One SSIM tile (+ fused pool). H compile-time. Offset space (x - 0.5).
// ---------------------------------------------------------------------------
template <int H, bool DO_POOL, bool SUB>
__device__ __forceinline__ void ssim_tile(
    SmemWS* ws,
    const float* __restrict__ P, const float* __restrict__ T,
    int level, int out_off, int ch, int bx, int by)
{
    constexpr int W = H;
    constexpr int OH = H - 10;
    const int t = threadIdx.x;

    const float* Pc = P + (size_t)ch * (H * W);
    const float* Tc = T + (size_t)ch * (H * W);

    ull W2[11];
#pragma unroll
    for (int i = 0; i < 11; i++) W2[i] = pk2(GW[i], GW[i]);

    // ---------------- Stage A: horizontal pass + fused pool ----------------
    {
        const int r  = t >> 2;
        const int c0 = (t & 3) * 8;
        const int gy = by + r;
        const bool rowok = gy < H;
        const float* rowP = Pc + (size_t)gy * W + bx + c0;
        const float* rowT = Tc + (size_t)gy * W + bx + c0;

        ull s01[8], s2[8];
        float plP[4], plT[4];
#pragma unroll
        for (int j = 0; j < 8; j++) { s01[j] = 0ULL; s2[j] = 0ULL; }

#pragma unroll
        for (int chk = 0; chk < 5; chk++) {
            float4 pv4 = make_float4(0.f, 0.f, 0.f, 0.f);
            float4 tv4 = make_float4(0.f, 0.f, 0.f, 0.f);
            int gx = bx + c0 + chk * 4;
            if (rowok && gx < W) {
                pv4 = *(const float4*)(rowP + chk * 4);
                tv4 = *(const float4*)(rowT + chk * 4);
            }
            if (SUB) {
                pv4.x -= 0.5f; pv4.y -= 0.5f; pv4.z -= 0.5f; pv4.w -= 0.5f;
                tv4.x -= 0.5f; tv4.y -= 0.5f; tv4.z -= 0.5f; tv4.w -= 0.5f;
            }

            if (DO_POOL && chk < 2) {
                plP[chk * 2 + 0] = pv4.x + pv4.y;
                plP[chk * 2 + 1] = pv4.z + pv4.w;
                plT[chk * 2 + 0] = tv4.x + tv4.y;
                plT[chk * 2 + 1] = tv4.z + tv4.w;
            }

            const float pa[4] = {pv4.x, pv4.y, pv4.z, pv4.w};
            const float ta[4] = {tv4.x, tv4.y, tv4.z, tv4.w};
#pragma unroll
            for (int q = 0; q < 4; q++) {
                const int k = chk * 4 + q;
                if (k < 18) {
                    float pv = pa[q], tv = ta[q];
                    ull ptp = pk2(pv, tv);
                    float ssv = fmaf(pv, pv, tv * tv);   // p^2 + t^2
                    float ptv = pv * tv;
                    ull ssp = pk2(ssv, ptv);
#pragma unroll
                    for (int j = 0; j < 8; j++) {
                        const int i = k - j;
                        if (i >= 0 && i <= 10) {
                            FMA2(s01[j], W2[i], ptp, s01[j]);
                            FMA2(s2[j],  W2[i], ssp, s2[j]);
                        }
                    }
                }
            }

            if (DO_POOL && chk == 1) {
                float vp[4], vt[4];
#pragma unroll
                for (int q = 0; q < 4; q++) {
                    vp[q] = plP[q] + __shfl_down_sync(0xffffffffu, plP[q], 4);
                    vt[q] = plT[q] + __shfl_down_sync(0xffffffffu, plT[q], 4);
                }
                if (((r & 1) == 0) && (gy + 1 < H)) {
                    constexpr int Ho = H >> 1;
                    size_t o = (size_t)ch * (Ho * Ho) + (size_t)(gy >> 1) * Ho
                               + ((bx + c0) >> 1);
                    *(float4*)(g_scr_p + out_off + o) =
                        make_float4(0.25f * vp[0], 0.25f * vp[1],
                                    0.25f * vp[2], 0.25f * vp[3]);
                    *(float4*)(g_scr_t + out_off + o) =
                        make_float4(0.25f * vt[0], 0.25f * vt[1],
                                    0.25f * vt[2], 0.25f * vt[3]);
                }
            }
        }
        // conflict-free swizzled STS.128: logical col c0+j -> swz(c0+j, r)
#pragma unroll
        for (int j = 0; j < 8; j++) {
            ws->hs[r][swz(c0 + j, r)] = make_ulonglong2(s01[j], s2[j]);
        }
    }
    __syncthreads();

    // ---------------- Stage B: vertical pass + SSIM ----------------
    const float C1v = 0.01f * 0.01f;
    const float C2v = 0.03f * 0.03f;
    float lsim = 0.f, lcs = 0.f;
    {
        const int tx = t & 31;
        const int g  = t >> 5;
        const int r0 = g * 7;
        const int cnt = (54 - r0) < 7 ? (54 - r0) : 7;
        const int ox = bx + tx;

        // two precomputed swizzled columns (row parity even/odd)
        int cols[2];
        cols[0] = swz(tx, 0);
        cols[1] = swz(tx, 1);

        ull a01[7], a2[7];
#pragma unroll
        for (int j = 0; j < 7; j++) { a01[j] = 0ULL; a2[j] = 0ULL; }

#pragma unroll
        for (int k = 0; k < 17; k++) {
            ulonglong2 h = ws->hs[r0 + k][cols[(r0 + k) & 1]];
#pragma unroll
            for (int j = 0; j < 7; j++) {
                const int i = k - j;
                if (i >= 0 && i <= 10) {
                    FMA2(a01[j], W2[i], h.x, a01[j]);
                    FMA2(a2[j],  W2[i], h.y, a2[j]);
                }
            }
        }

#pragma unroll
        for (int j = 0; j < 7; j++) {
            int oy = by + r0 + j;
            if (j < cnt && oy < OH && ox < OH) {
                float m1o, m2o, ssq, spt;
                upk2(a01[j], m1o, m2o);
                upk2(a2[j],  ssq, spt);
                float s12 = spt - m1o * m2o;
                float v2  = ssq - m1o * m1o - m2o * m2o + C2v;
                float m1 = m1o + 0.5f, m2 = m2o + 0.5f;
                float m1s = m1 * m1, m2s = m2 * m2, m12 = m1 * m2;
                float v1 = 2.f * s12 + C2v;
                float cs  = __fdividef(v1, v2);
                float sim = cs * __fdividef(2.f * m12 + C1v, m1s + m2s + C1v);
                lcs  += cs;
                lsim += sim;
            }
        }
    }

#pragma unroll
    for (int o = 16; o > 0; o >>= 1) {
        lsim += __shfl_down_sync(0xffffffff, lsim, o);
        lcs  += __shfl_down_sync(0xffffffff, lcs, o);
    }
    if ((t & 31) == 0) { ws->rs[t >> 5] = lsim; ws->rc[t >> 5] = lcs; }
    __syncthreads();
    if (t == 0) {
        float ss = 0.f, cc = 0.f;
#pragma unroll
        for (int i = 0; i < 8; i++) { ss += ws->rs[i]; cc += ws->rc[i]; }
        atomicAdd(&g_sim_acc[level * NCH + ch], ss);
        atomicAdd(&g_cs_acc[level * NCH + ch], cc);
    }
    __syncthreads();
}

// ---------------------------------------------------------------------------
// L0 / L1: standalone, one tile per CTA.
// ---------------------------------------------------------------------------
__global__ __launch_bounds__(256, 3)
void ssim_l0_kernel(const float* __restrict__ P, const float* __restrict__ T)
{
    __shared__ SmemWS ws;
    ssim_tile<1024, true, true>(&ws, P, T, 0, OFF_L1,
                                blockIdx.z, blockIdx.x * TX, blockIdx.y * TY);
}

__global__ __launch_bounds__(256, 3)
void ssim_l1_kernel()
{
    __shared__ SmemWS ws;
    ssim_tile<512, true, false>(&ws, g_scr_p + OFF_L1, g_scr_t + OFF_L1,
                                1, OFF_L2,
                                blockIdx.z, blockIdx.x * TX, blockIdx.y * TY);
}

// ---------------------------------------------------------------------------
// Persistent kernel: levels 2..4 with grid barriers, then fp32 combine.
// ---------------------------------------------------------------------------
template <int H, bool DO_POOL>
__device__ __forceinline__ void run_level(SmemWS* ws, int level,
                                          int in_off, int out_off)
{
    constexpr int gx  = (H - 10 + TX - 1) / TX;
    constexpr int gyn = (H - 10 + TY - 1) / TY;
    constexpr int per_ch = gx * gyn;
    constexpr int tiles = per_ch * NCH;
    const float* Pl = (const float*)(g_scr_p + in_off);
    const float* Tl = (const float*)(g_scr_t + in_off);

#pragma unroll 1
    for (int w = blockIdx.x; w < tiles; w += gridDim.x) {
        int ch  = w / per_ch;
        int rem = w - ch * per_ch;
        int tyI = rem / gx;
        int txI = rem - tyI * gx;
        ssim_tile<H, DO_POOL, false>(ws, Pl, Tl, level, out_off,
                                     ch, txI * TX, tyI * TY);
    }
}

__global__ __launch_bounds__(256, 3)
void ssim_rest_kernel(float* __restrict__ out)
{
    __shared__ SmemWS ws;   // single instance shared by all instantiations

    run_level<256, true >(&ws, 2, OFF_L2, OFF_L3);
    grid_barrier();
    run_level<128, true >(&ws, 3, OFF_L3, OFF_L4);
    grid_barrier();
    run_level<64,  false>(&ws, 4, OFF_L4, 0);
    grid_barrier();

    // fp32 combine: thread c (<10) handles category c.
    if (blockIdx.x == 0) {
        __shared__ float part[NCH];
        const int t = threadIdx.x;
        if (t < NCH) {
            const float w[5]    = {0.0448f, 0.2856f, 0.3001f, 0.2363f, 0.1333f};
            const float icnt[5] = {1.f / (1014.f * 1014.f), 1.f / (502.f * 502.f),
                                   1.f / (246.f * 246.f),  1.f / (118.f * 118.f),
                                   1.f / (54.f * 54.f)};
            float ms4 = g_sim_acc[4 * NCH + t] * icnt[4];
            float e = 4.0f * w[4] * log2f(ms4);
            for (int l = 0; l < 4; l++) {
                float mc = g_cs_acc[l * NCH + t] * icnt[l];
                e += w[l] * log2f(mc);
            }
            part[t] = exp2f(e);
        }
        __syncthreads();
        if (t == 0) {
            float total = 0.f;
            for (int c = 0; c < NCH; c++) total += part[c];
            out[0] = 1.0f - total;
        }
        if (t < 50) { g_sim_acc[t] = 0.f; g_cs_acc[t] = 0.f; }
    }
}

extern "C" void kernel_launch(void* const* d_in, const int* in_sizes, int n_in,
                              void* d_out, int out_size)
{
    const float* P = (const float*)d_in[0];
    const float* T = (const float*)d_in[1];
    float* out = (float*)d_out;

    dim3 grid0(32, 19, NCH);   // L0: 1024 -> OH 1014
    ssim_l0_kernel<<<grid0, 256>>>(P, T);
    dim3 grid1(16, 10, NCH);   // L1: 512 -> OH 502
    ssim_l1_kernel<<<grid1, 256>>>();
    ssim_rest_kernel<<<NBLK2, 256>>>(out);
}

// round 12
// speedup vs baseline: 3.1706x; 1.0706x over previous
#include <cuda_runtime.h>
#include <math.h>

// ---------------------------------------------------------------------------
// MS-SSIM loss. 10 channels 1024x1024 fp32, 5 levels.
// L0, L1: standalone kernels @ 4 CTAs/SM (reg diet: 6-entry symmetric weight
// table). L2-L4 + combine: persistent kernel w/ barriers @ 3 CTAs/SM.
// 4-conv formulation, packed f32x2 FMA, ulonglong2 swizzled smem, fused pool.
// ---------------------------------------------------------------------------

#define NCH 10
#define TX 32
#define TY 54
#define NBLK2 400

__device__ constexpr float GW[11] = {
    0.00102842f, 0.00759877f, 0.03600077f, 0.10936076f, 0.21300535f,
    0.26601172f,
    0.21300535f, 0.10936076f, 0.03600077f, 0.00759877f, 0.00102842f};

__device__ float g_sim_acc[50];   // [level][channel]
__device__ float g_cs_acc[50];
__device__ int g_bar_count;
__device__ int g_bar_gen;

#define SCR_TOTAL 3481600
__device__ __align__(16) float g_scr_p[SCR_TOTAL];
__device__ __align__(16) float g_scr_t[SCR_TOTAL];

#define OFF_L1 0
#define OFF_L2 2621440
#define OFF_L3 3276800
#define OFF_L4 3440640

// shared workspace: 66*32*16 + 64 = ~33.9 KB
struct SmemWS {
    ulonglong2 hs[66][32];   // (s01, s2) packed pairs, bank-swizzled columns
    float rs[8], rc[8];
};

__device__ __forceinline__ int swz(int col, int row) {
    return (col & 24) | (((col & 7) + ((col >> 3) & 3) + ((row & 1) << 2)) & 7);
}

// ---- f32x2 packed math helpers --------------------------------------------
typedef unsigned long long ull;

__device__ __forceinline__ ull pk2(float a, float b) {
    ull r; asm("mov.b64 %0, {%1, %2};" : "=l"(r) : "f"(a), "f"(b)); return r;
}
__device__ __forceinline__ void upk2(ull v, float& a, float& b) {
    asm("mov.b64 {%0, %1}, %2;" : "=f"(a), "=f"(b) : "l"(v));
}
#define FMA2(d, a, b, c) \
    asm("fma.rn.f32x2 %0, %1, %2, %3;" : "=l"(d) : "l"(a), "l"(b), "l"(c))

__device__ __forceinline__ void grid_barrier()
{
    __syncthreads();
    if (threadIdx.x == 0) {
        __threadfence();
        int gen = *((volatile int*)&g_bar_gen);
        if (atomicAdd(&g_bar_count, 1) == (int)gridDim.x - 1) {
            g_bar_count = 0;
            __threadfence();
            atomicAdd(&g_bar_gen, 1);
        } else {
            while (*((volatile int*)&g_bar_gen) == gen) { __nanosleep(128); }
        }
        __threadfence();
    }
    __syncthreads();
}

// ---------------------------------------------------------------------------
// One SSIM tile (+ fused pool). H compile-time. Offset space (x - 0.5).
// Weight table: 6 unique entries (gaussian symmetric); index folded at
// compile time (all tap loops fully unrolled).
// ---------------------------------------------------------------------------
template <int H, bool DO_POOL, bool SUB>
__device__ __forceinline__ void ssim_tile(
    SmemWS* ws,
    const float* __restrict__ P, const float* __restrict__ T,
    int level, int out_off, int ch, int bx, int by)
{
    constexpr int W = H;
    constexpr int OH = H - 10;
    const int t = threadIdx.x;

    const float* Pc = P + (size_t)ch * (H * W);
    const float* Tc = T + (size_t)ch * (H * W);

    ull W2[6];
#pragma unroll
    for (int i = 0; i < 6; i++) W2[i] = pk2(GW[i], GW[i]);
#define W2AT(i) W2[(i) < 6 ? (i) : 10 - (i)]

    // ---------------- Stage A: horizontal pass + fused pool ----------------
    {
        const int r  = t >> 2;
        const int c0 = (t & 3) * 8;
        const int gy = by + r;
        const bool rowok = gy < H;
        const float* rowP = Pc + (size_t)gy * W + bx + c0;
        const float* rowT = Tc + (size_t)gy * W + bx + c0;

        ull s01[8], s2[8];
        float plP[4], plT[4];
#pragma unroll
        for (int j = 0; j < 8; j++) { s01[j] = 0ULL; s2[j] = 0ULL; }

#pragma unroll
        for (int chk = 0; chk < 5; chk++) {
            float4 pv4 = make_float4(0.f, 0.f, 0.f, 0.f);
            float4 tv4 = make_float4(0.f, 0.f, 0.f, 0.f);
            int gx = bx + c0 + chk * 4;
            if (rowok && gx < W) {
                pv4 = *(const float4*)(rowP + chk * 4);
                tv4 = *(const float4*)(rowT + chk * 4);
            }
            if (SUB) {
                pv4.x -= 0.5f; pv4.y -= 0.5f; pv4.z -= 0.5f; pv4.w -= 0.5f;
                tv4.x -= 0.5f; tv4.y -= 0.5f; tv4.z -= 0.5f; tv4.w -= 0.5f;
            }

            if (DO_POOL && chk < 2) {
                plP[chk * 2 + 0] = pv4.x + pv4.y;
                plP[chk * 2 + 1] = pv4.z + pv4.w;
                plT[chk * 2 + 0] = tv4.x + tv4.y;
                plT[chk * 2 + 1] = tv4.z + tv4.w;
            }

            const float pa[4] = {pv4.x, pv4.y, pv4.z, pv4.w};
            const float ta[4] = {tv4.x, tv4.y, tv4.z, tv4.w};
#pragma unroll
            for (int q = 0; q < 4; q++) {
                const int k = chk * 4 + q;
                if (k < 18) {
                    float pv = pa[q], tv = ta[q];
                    ull ptp = pk2(pv, tv);
                    float ssv = fmaf(pv, pv, tv * tv);   // p^2 + t^2
                    float ptv = pv * tv;
                    ull ssp = pk2(ssv, ptv);
#pragma unroll
                    for (int j = 0; j < 8; j++) {
                        const int i = k - j;
                        if (i >= 0 && i <= 10) {
                            FMA2(s01[j], W2AT(i), ptp, s01[j]);
                            FMA2(s2[j],  W2AT(i), ssp, s2[j]);
                        }
                    }
                }
            }

            if (DO_POOL && chk == 1) {
                float vp[4], vt[4];
#pragma unroll
                for (int q = 0; q < 4; q++) {
                    vp[q] = plP[q] + __shfl_down_sync(0xffffffffu, plP[q], 4);
                    vt[q] = plT[q] + __shfl_down_sync(0xffffffffu, plT[q], 4);
                }
                if (((r & 1) == 0) && (gy + 1 < H)) {
                    constexpr int Ho = H >> 1;
                    size_t o = (size_t)ch * (Ho * Ho) + (size_t)(gy >> 1) * Ho
                               + ((bx + c0) >> 1);
                    *(float4*)(g_scr_p + out_off + o) =
                        make_float4(0.25f * vp[0], 0.25f * vp[1],
                                    0.25f * vp[2], 0.25f * vp[3]);
                    *(float4*)(g_scr_t + out_off + o) =
                        make_float4(0.25f * vt[0], 0.25f * vt[1],
                                    0.25f * vt[2], 0.25f * vt[3]);
                }
            }
        }
#pragma unroll
        for (int j = 0; j < 8; j++) {
            ws->hs[r][swz(c0 + j, r)] = make_ulonglong2(s01[j], s2[j]);
        }
    }
    __syncthreads();

    // ---------------- Stage B: vertical pass + SSIM ----------------
    const float C1v = 0.01f * 0.01f;
    const float C2v = 0.03f * 0.03f;
    float lsim = 0.f, lcs = 0.f;
    {
        const int tx = t & 31;
        const int g  = t >> 5;
        const int r0 = g * 7;
        const int cnt = (54 - r0) < 7 ? (54 - r0) : 7;
        const int ox = bx + tx;

        int cols[2];
        cols[0] = swz(tx, 0);
        cols[1] = swz(tx, 1);

        ull a01[7], a2[7];
#pragma unroll
        for (int j = 0; j < 7; j++) { a01[j] = 0ULL; a2[j] = 0ULL; }

#pragma unroll
        for (int k = 0; k < 17; k++) {
            ulonglong2 h = ws->hs[r0 + k][cols[(r0 + k) & 1]];
#pragma unroll
            for (int j = 0; j < 7; j++) {
                const int i = k - j;
                if (i >= 0 && i <= 10) {
                    FMA2(a01[j], W2AT(i), h.x, a01[j]);
                    FMA2(a2[j],  W2AT(i), h.y, a2[j]);
                }
            }
        }

#pragma unroll
        for (int j = 0; j < 7; j++) {
            int oy = by + r0 + j;
            if (j < cnt && oy < OH && ox < OH) {
                float m1o, m2o, ssq, spt;
                upk2(a01[j], m1o, m2o);
                upk2(a2[j],  ssq, spt);
                float s12 = spt - m1o * m2o;
                float v2  = ssq - m1o * m1o - m2o * m2o + C2v;
                float m1 = m1o + 0.5f, m2 = m2o + 0.5f;
                float m1s = m1 * m1, m2s = m2 * m2, m12 = m1 * m2;
                float v1 = 2.f * s12 + C2v;
                float cs  = __fdividef(v1, v2);
                float sim = cs * __fdividef(2.f * m12 + C1v, m1s + m2s + C1v);
                lcs  += cs;
                lsim += sim;
            }
        }
    }

#pragma unroll
    for (int o = 16; o > 0; o >>= 1) {
        lsim += __shfl_down_sync(0xffffffff, lsim, o);
        lcs  += __shfl_down_sync(0xffffffff, lcs, o);
    }
    if ((t & 31) == 0) { ws->rs[t >> 5] = lsim; ws->rc[t >> 5] = lcs; }
    __syncthreads();
    if (t == 0) {
        float ss = 0.f, cc = 0.f;
#pragma unroll
        for (int i = 0; i < 8; i++) { ss += ws->rs[i]; cc += ws->rc[i]; }
        atomicAdd(&g_sim_acc[level * NCH + ch], ss);
        atomicAdd(&g_cs_acc[level * NCH + ch], cc);
    }
    __syncthreads();
#undef W2AT
}

// ---------------------------------------------------------------------------
// L0 / L1: standalone, one tile per CTA, 4 CTAs/SM target.
// ---------------------------------------------------------------------------
__global__ __launch_bounds__(256, 4)
void ssim_l0_kernel(const float* __restrict__ P, const float* __restrict__ T)
{
    __shared__ SmemWS ws;
    ssim_tile<1024, true, true>(&ws, P, T, 0, OFF_L1,
                                blockIdx.z, blockIdx.x * TX, blockIdx.y * TY);
}

__global__ __launch_bounds__(256, 4)
void ssim_l1_kernel()
{
    __shared__ SmemWS ws;
    ssim_tile<512, true, false>(&ws, g_scr_p + OFF_L1, g_scr_t + OFF_L1,
                                1, OFF_L2,
                                blockIdx.z, blockIdx.x * TX, blockIdx.y * TY);
}

// ---------------------------------------------------------------------------
// Persistent kernel: levels 2..4 with grid barriers, then fp32 combine.
// ---------------------------------------------------------------------------
template <int H, bool DO_POOL>
__device__ __forceinline__ void run_level(SmemWS* ws, int level,
                                          int in_off, int out_off)
{
    constexpr int gx  = (H - 10 + TX - 1) / TX;
    constexpr int gyn = (H - 10 + TY - 1) / TY;
    constexpr int per_ch = gx * gyn;
    constexpr int tiles = per_ch * NCH;
    const float* Pl = (const float*)(g_scr_p + in_off);
    const float* Tl = (const float*)(g_scr_t + in_off);

#pragma unroll 1
    for (int w = blockIdx.x; w < tiles; w += gridDim.x) {
        int ch  = w / per_ch;
        int rem = w - ch * per_ch;
        int tyI = rem / gx;
        int txI = rem - tyI * gx;
        ssim_tile<H, DO_POOL, false>(ws, Pl, Tl, level, out_off,
                                     ch, txI * TX, tyI * TY);
    }
}

__global__ __launch_bounds__(256, 3)
void ssim_rest_kernel(float* __restrict__ out)
{
    __shared__ SmemWS ws;

    run_level<256, true >(&ws, 2, OFF_L2, OFF_L3);
    grid_barrier();
    run_level<128, true >(&ws, 3, OFF_L3, OFF_L4);
    grid_barrier();
    run_level<64,  false>(&ws, 4, OFF_L4, 0);
    grid_barrier();

    // fp32 combine: thread c (<10) handles category c.
    if (blockIdx.x == 0) {
        __shared__ float part[NCH];
        const int t = threadIdx.x;
        if (t < NCH) {
            const float w[5]    = {0.0448f, 0.2856f, 0.3001f, 0.2363f, 0.1333f};
            const float icnt[5] = {1.f / (1014.f * 1014.f), 1.f / (502.f * 502.f),
                                   1.f / (246.f * 246.f),  1.f / (118.f * 118.f),
                                   1.f / (54.f * 54.f)};
            float ms4 = g_sim_acc[4 * NCH + t] * icnt[4];
            float e = 4.0f * w[4] * log2f(ms4);
            for (int l = 0; l < 4; l++) {
                float mc = g_cs_acc[l * NCH + t] * icnt[l];
                e += w[l] * log2f(mc);
            }
            part[t] = exp2f(e);
        }
        __syncthreads();
        if (t == 0) {
            float total = 0.f;
            for (int c = 0; c < NCH; c++) total += part[c];
            out[0] = 1.0f - total;
        }
        if (t < 50) { g_sim_acc[t] = 0.f; g_cs_acc[t] = 0.f; }
    }
}

extern "C" void kernel_launch(void* const* d_in, const int* in_sizes, int n_in,
                              void* d_out, int out_size)
{
    const float* P = (const float*)d_in[0];
    const float* T = (const float*)d_in[1];
    float* out = (float*)d_out;

    dim3 grid0(32, 19, NCH);   // L0: 1024 -> OH 1014
    ssim_l0_kernel<<<grid0, 256>>>(P, T);
    dim3 grid1(16, 10, NCH);   // L1: 512 -> OH 502
    ssim_l1_kernel<<<grid1, 256>>>();
    ssim_rest_kernel<<<NBLK2, 256>>>(out);
}

// round 13
// speedup vs baseline: 3.1863x; 1.0050x over previous
#include <cuda_runtime.h>
#include <math.h>

// ---------------------------------------------------------------------------
// MS-SSIM loss. 10 channels 1024x1024 fp32, 5 levels.
// L0, L1: standalone kernels @ 4 CTAs/SM, chunk-prefetch Stage A.
// L2-L4 + combine: persistent kernel; small TY tiles for L3/L4 parallelism.
// 4-conv formulation, packed f32x2 FMA, ulonglong2 swizzled smem, fused pool.
// ---------------------------------------------------------------------------

#define NCH 10
#define TX 32
#define NBLK2 400

__device__ constexpr float GW[11] = {
    0.00102842f, 0.00759877f, 0.03600077f, 0.10936076f, 0.21300535f,
    0.26601172f,
    0.21300535f, 0.10936076f, 0.03600077f, 0.00759877f, 0.00102842f};

__device__ float g_sim_acc[50];   // [level][channel]
__device__ float g_cs_acc[50];
__device__ int g_bar_count;
__device__ int g_bar_gen;

#define SCR_TOTAL 3481600
__device__ __align__(16) float g_scr_p[SCR_TOTAL];
__device__ __align__(16) float g_scr_t[SCR_TOTAL];

#define OFF_L1 0
#define OFF_L2 2621440
#define OFF_L3 3276800
#define OFF_L4 3440640

// shared workspace sized for the largest tile (TY=54 -> 66 buffer rows)
struct SmemWS {
    ulonglong2 hs[66][32];   // (s01, s2) packed pairs, bank-swizzled columns
    float rs[8], rc[8];
};

__device__ __forceinline__ int swz(int col, int row) {
    return (col & 24) | (((col & 7) + ((col >> 3) & 3) + ((row & 1) << 2)) & 7);
}

// ---- f32x2 packed math helpers --------------------------------------------
typedef unsigned long long ull;

__device__ __forceinline__ ull pk2(float a, float b) {
    ull r; asm("mov.b64 %0, {%1, %2};" : "=l"(r) : "f"(a), "f"(b)); return r;
}
__device__ __forceinline__ void upk2(ull v, float& a, float& b) {
    asm("mov.b64 {%0, %1}, %2;" : "=f"(a), "=f"(b) : "l"(v));
}
#define FMA2(d, a, b, c) \
    asm("fma.rn.f32x2 %0, %1, %2, %3;" : "=l"(d) : "l"(a), "l"(b), "l"(c))
#define W2AT(i) W2[(i) < 6 ? (i) : 10 - (i)]

__device__ __forceinline__ void grid_barrier()
{
    __syncthreads();
    if (threadIdx.x == 0) {
        __threadfence();
        int gen = *((volatile int*)&g_bar_gen);
        if (atomicAdd(&g_bar_count, 1) == (int)gridDim.x - 1) {
            g_bar_count = 0;
            __threadfence();
            atomicAdd(&g_bar_gen, 1);
        } else {
            while (*((volatile int*)&g_bar_gen) == gen) { __nanosleep(128); }
        }
        __threadfence();
    }
    __syncthreads();
}

// ---------------------------------------------------------------------------
// One SSIM tile (+ fused pool). H, TY compile-time. Offset space (x - 0.5).
// ---------------------------------------------------------------------------
template <int H, int TYV, bool DO_POOL, bool SUB, bool PERSIST>
__device__ __forceinline__ void ssim_tile(
    SmemWS* ws,
    const float* __restrict__ P, const float* __restrict__ T,
    int level, int out_off, int ch, int bx, int by)
{
    constexpr int W = H;
    constexpr int OH = H - 10;
    constexpr int ROWS = TYV + 10;           // input rows needed
    constexpr int OUT_PER = (TYV + 7) / 8;   // outputs per Stage-B thread
    const int t = threadIdx.x;

    const float* Pc = P + (size_t)ch * (H * W);
    const float* Tc = T + (size_t)ch * (H * W);

    ull W2[6];
#pragma unroll
    for (int i = 0; i < 6; i++) W2[i] = pk2(GW[i], GW[i]);

    // ---------------- Stage A: horizontal pass + fused pool ----------------
    {
        const int r  = t >> 2;
        const int c0 = (t & 3) * 8;
        const int gy = by + r;
        const bool rowok = (r < ROWS) && (gy < H);
        const float* rowP = Pc + (size_t)gy * W + bx + c0;
        const float* rowT = Tc + (size_t)gy * W + bx + c0;

        ull s01[8], s2[8];
        float plP[4], plT[4];
#pragma unroll
        for (int j = 0; j < 8; j++) { s01[j] = 0ULL; s2[j] = 0ULL; }

        // chunk 0 preload
        float4 pv4 = make_float4(0.f, 0.f, 0.f, 0.f);
        float4 tv4 = make_float4(0.f, 0.f, 0.f, 0.f);
        if (rowok && (bx + c0) < W) {
            pv4 = *(const float4*)(rowP);
            tv4 = *(const float4*)(rowT);
        }

#pragma unroll
        for (int chk = 0; chk < 5; chk++) {
            // prefetch chunk chk+1 (distance-1 software pipeline)
            float4 npv = make_float4(0.f, 0.f, 0.f, 0.f);
            float4 ntv = make_float4(0.f, 0.f, 0.f, 0.f);
            if (chk < 4) {
                int ngx = bx + c0 + (chk + 1) * 4;
                if (rowok && ngx < W) {
                    npv = *(const float4*)(rowP + (chk + 1) * 4);
                    ntv = *(const float4*)(rowT + (chk + 1) * 4);
                }
            }

            if (SUB) {
                pv4.x -= 0.5f; pv4.y -= 0.5f; pv4.z -= 0.5f; pv4.w -= 0.5f;
                tv4.x -= 0.5f; tv4.y -= 0.5f; tv4.z -= 0.5f; tv4.w -= 0.5f;
            }

            if (DO_POOL && chk < 2) {
                plP[chk * 2 + 0] = pv4.x + pv4.y;
                plP[chk * 2 + 1] = pv4.z + pv4.w;
                plT[chk * 2 + 0] = tv4.x + tv4.y;
                plT[chk * 2 + 1] = tv4.z + tv4.w;
            }

            const float pa[4] = {pv4.x, pv4.y, pv4.z, pv4.w};
            const float ta[4] = {tv4.x, tv4.y, tv4.z, tv4.w};
#pragma unroll
            for (int q = 0; q < 4; q++) {
                const int k = chk * 4 + q;
                if (k < 18) {
                    float pv = pa[q], tv = ta[q];
                    ull ptp = pk2(pv, tv);
                    float ssv = fmaf(pv, pv, tv * tv);   // p^2 + t^2
                    float ptv = pv * tv;
                    ull ssp = pk2(ssv, ptv);
#pragma unroll
                    for (int j = 0; j < 8; j++) {
                        const int i = k - j;
                        if (i >= 0 && i <= 10) {
                            FMA2(s01[j], W2AT(i), ptp, s01[j]);
                            FMA2(s2[j],  W2AT(i), ssp, s2[j]);
                        }
                    }
                }
            }

            if (DO_POOL && chk == 1) {
                float vp[4], vt[4];
#pragma unroll
                for (int q = 0; q < 4; q++) {
                    vp[q] = plP[q] + __shfl_down_sync(0xffffffffu, plP[q], 4);
                    vt[q] = plT[q] + __shfl_down_sync(0xffffffffu, plT[q], 4);
                }
                if (((r & 1) == 0) && (r + 1 < ROWS) && (gy + 1 < H)) {
                    constexpr int Ho = H >> 1;
                    size_t o = (size_t)ch * (Ho * Ho) + (size_t)(gy >> 1) * Ho
                               + ((bx + c0) >> 1);
                    *(float4*)(g_scr_p + out_off + o) =
                        make_float4(0.25f * vp[0], 0.25f * vp[1],
                                    0.25f * vp[2], 0.25f * vp[3]);
                    *(float4*)(g_scr_t + out_off + o) =
                        make_float4(0.25f * vt[0], 0.25f * vt[1],
                                    0.25f * vt[2], 0.25f * vt[3]);
                }
            }
            pv4 = npv; tv4 = ntv;
        }
#pragma unroll
        for (int j = 0; j < 8; j++) {
            ws->hs[r][swz(c0 + j, r)] = make_ulonglong2(s01[j], s2[j]);
        }
    }
    __syncthreads();

    // ---------------- Stage B: vertical pass + SSIM ----------------
    const float C1v = 0.01f * 0.01f;
    const float C2v = 0.03f * 0.03f;
    float lsim = 0.f, lcs = 0.f;
    {
        const int tx = t & 31;
        const int g  = t >> 5;
        const int r0 = g * OUT_PER;
        const int cnt = (TYV - r0) < OUT_PER ? (TYV - r0) : OUT_PER;
        const int ox = bx + tx;

        int cols[2];
        cols[0] = swz(tx, 0);
        cols[1] = swz(tx, 1);

        ull a01[OUT_PER], a2[OUT_PER];
#pragma unroll
        for (int j = 0; j < OUT_PER; j++) { a01[j] = 0ULL; a2[j] = 0ULL; }

#pragma unroll
        for (int k = 0; k < OUT_PER + 10; k++) {
            ulonglong2 h = ws->hs[r0 + k][cols[(r0 + k) & 1]];
#pragma unroll
            for (int j = 0; j < OUT_PER; j++) {
                const int i = k - j;
                if (i >= 0 && i <= 10) {
                    FMA2(a01[j], W2AT(i), h.x, a01[j]);
                    FMA2(a2[j],  W2AT(i), h.y, a2[j]);
                }
            }
        }

#pragma unroll
        for (int j = 0; j < OUT_PER; j++) {
            int oy = by + r0 + j;
            if (j < cnt && oy < OH && ox < OH) {
                float m1o, m2o, ssq, spt;
                upk2(a01[j], m1o, m2o);
                upk2(a2[j],  ssq, spt);
                float s12 = spt - m1o * m2o;
                float v2  = ssq - m1o * m1o - m2o * m2o + C2v;
                float m1 = m1o + 0.5f, m2 = m2o + 0.5f;
                float m1s = m1 * m1, m2s = m2 * m2, m12 = m1 * m2;
                float v1 = 2.f * s12 + C2v;
                float cs  = __fdividef(v1, v2);
                float sim = cs * __fdividef(2.f * m12 + C1v, m1s + m2s + C1v);
                lcs  += cs;
                lsim += sim;
            }
        }
    }

#pragma unroll
    for (int o = 16; o > 0; o >>= 1) {
        lsim += __shfl_down_sync(0xffffffff, lsim, o);
        lcs  += __shfl_down_sync(0xffffffff, lcs, o);
    }
    if ((t & 31) == 0) { ws->rs[t >> 5] = lsim; ws->rc[t >> 5] = lcs; }
    __syncthreads();
    if (t == 0) {
        float ss = 0.f, cc = 0.f;
#pragma unroll
        for (int i = 0; i < 8; i++) { ss += ws->rs[i]; cc += ws->rc[i]; }
        atomicAdd(&g_sim_acc[level * NCH + ch], ss);
        atomicAdd(&g_cs_acc[level * NCH + ch], cc);
    }
    if (PERSIST) __syncthreads();   // protect smem reuse in persistent loop
}

// ---------------------------------------------------------------------------
// L0 / L1: standalone, one tile per CTA, 4 CTAs/SM target.
// ---------------------------------------------------------------------------
__global__ __launch_bounds__(256, 4)
void ssim_l0_kernel(const float* __restrict__ P, const float* __restrict__ T)
{
    __shared__ SmemWS ws;
    ssim_tile<1024, 54, true, true, false>(
        &ws, P, T, 0, OFF_L1, blockIdx.z, blockIdx.x * TX, blockIdx.y * 54);
}

__global__ __launch_bounds__(256, 4)
void ssim_l1_kernel()
{
    __shared__ SmemWS ws;
    ssim_tile<512, 54, true, false, false>(
        &ws, g_scr_p + OFF_L1, g_scr_t + OFF_L1, 1, OFF_L2,
        blockIdx.z, blockIdx.x * TX, blockIdx.y * 54);
}

// ---------------------------------------------------------------------------
// Persistent kernel: levels 2..4 with grid barriers, then fp32 combine.
// Small TY for L3/L4 to spread tiles over the grid.
// ---------------------------------------------------------------------------
template <int H, int TYV, bool DO_POOL>
__device__ __forceinline__ void run_level(SmemWS* ws, int level,
                                          int in_off, int out_off)
{
    constexpr int gx  = (H - 10 + TX - 1) / TX;
    constexpr int gyn = (H - 10 + TYV - 1) / TYV;
    constexpr int per_ch = gx * gyn;
    constexpr int tiles = per_ch * NCH;
    const float* Pl = (const float*)(g_scr_p + in_off);
    const float* Tl = (const float*)(g_scr_t + in_off);

#pragma unroll 1
    for (int w = blockIdx.x; w < tiles; w += gridDim.x) {
        int ch  = w / per_ch;
        int rem = w - ch * per_ch;
        int tyI = rem / gx;
        int txI = rem - tyI * gx;
        ssim_tile<H, TYV, DO_POOL, false, true>(ws, Pl, Tl, level, out_off,
                                                ch, txI * TX, tyI * TYV);
    }
}

__global__ __launch_bounds__(256, 3)
void ssim_rest_kernel(float* __restrict__ out)
{
    __shared__ SmemWS ws;

    run_level<256, 54, true >(&ws, 2, OFF_L2, OFF_L3);   // 400 tiles
    grid_barrier();
    run_level<128, 28, true >(&ws, 3, OFF_L3, OFF_L4);   // 200 tiles
    grid_barrier();
    run_level<64,  14, false>(&ws, 4, OFF_L4, 0);        // 80 tiles
    grid_barrier();

    // fp32 combine: thread c (<10) handles category c.
    if (blockIdx.x == 0) {
        __shared__ float part[NCH];
        const int t = threadIdx.x;
        if (t < NCH) {
            const float w[5]    = {0.0448f, 0.2856f, 0.3001f, 0.2363f, 0.1333f};
            const float icnt[5] = {1.f / (1014.f * 1014.f), 1.f / (502.f * 502.f),
                                   1.f / (246.f * 246.f),  1.f / (118.f * 118.f),
                                   1.f / (54.f * 54.f)};
            float ms4 = g_sim_acc[4 * NCH + t] * icnt[4];
            float e = 4.0f * w[4] * log2f(ms4);
            for (int l = 0; l < 4; l++) {
                float mc = g_cs_acc[l * NCH + t] * icnt[l];
                e += w[l] * log2f(mc);
            }
            part[t] = exp2f(e);
        }
        __syncthreads();
        if (t == 0) {
            float total = 0.f;
            for (int c = 0; c < NCH; c++) total += part[c];
            out[0] = 1.0f - total;
        }
        if (t < 50) { g_sim_acc[t] = 0.f; g_cs_acc[t] = 0.f; }
    }
}

extern "C" void kernel_launch(void* const* d_in, const int* in_sizes, int n_in,
                              void* d_out, int out_size)
{
    const float* P = (const float*)d_in[0];
    const float* T = (const float*)d_in[1];
    float* out = (float*)d_out;

    dim3 grid0(32, 19, NCH);   // L0: 1024 -> OH 1014
    ssim_l0_kernel<<<grid0, 256>>>(P, T);
    dim3 grid1(16, 10, NCH);   // L1: 512 -> OH 502
    ssim_l1_kernel<<<grid1, 256>>>();
    ssim_rest_kernel<<<NBLK2, 256>>>(out);
}

// round 14
// speedup vs baseline: 3.3108x; 1.0391x over previous
#include <cuda_runtime.h>
#include <math.h>

// ---------------------------------------------------------------------------
// MS-SSIM loss. 10 channels 1024x1024 fp32, 5 levels.
// L0, L1: standalone @ 4 CTAs/SM; interior-tile specialization (no bounds
// predicates on 92% of tiles). L2-L4 + combine: persistent kernel.
// 4-conv formulation, packed f32x2 FMA, swizzled ulonglong2 smem with
// immediate-offset Stage-B loads, fused 2x2 pool, offset-0.5 trick.
// ---------------------------------------------------------------------------

#define NCH 10
#define TX 32
#define NBLK2 400

__device__ constexpr float GW[11] = {
    0.00102842f, 0.00759877f, 0.03600077f, 0.10936076f, 0.21300535f,
    0.26601172f,
    0.21300535f, 0.10936076f, 0.03600077f, 0.00759877f, 0.00102842f};

__device__ float g_sim_acc[50];   // [level][channel]
__device__ float g_cs_acc[50];
__device__ int g_bar_count;
__device__ int g_bar_gen;

#define SCR_TOTAL 3481600
__device__ __align__(16) float g_scr_p[SCR_TOTAL];
__device__ __align__(16) float g_scr_t[SCR_TOTAL];

#define OFF_L1 0
#define OFF_L2 2621440
#define OFF_L3 3276800
#define OFF_L4 3440640

// shared workspace sized for the largest tile (TY=54 -> 64 rows + 2 spare)
struct SmemWS {
    ulonglong2 hs[66][32];   // (s01, s2) packed pairs, bank-swizzled columns
    float rs[8], rc[8];
};

// swizzled column: swz(col,row) = (col&24) | (((col&7)+((col>>3)&3)+4(row&1))&7)
__device__ __forceinline__ int swz(int col, int row) {
    return (col & 24) | (((col & 7) + ((col >> 3) & 3) + ((row & 1) << 2)) & 7);
}

// ---- f32x2 packed math helpers --------------------------------------------
typedef unsigned long long ull;

__device__ __forceinline__ ull pk2(float a, float b) {
    ull r; asm("mov.b64 %0, {%1, %2};" : "=l"(r) : "f"(a), "f"(b)); return r;
}
__device__ __forceinline__ void upk2(ull v, float& a, float& b) {
    asm("mov.b64 {%0, %1}, %2;" : "=f"(a), "=f"(b) : "l"(v));
}
#define FMA2(d, a, b, c) \
    asm("fma.rn.f32x2 %0, %1, %2, %3;" : "=l"(d) : "l"(a), "l"(b), "l"(c))
#define W2AT(i) W2[(i) < 6 ? (i) : 10 - (i)]

__device__ __forceinline__ void grid_barrier()
{
    __syncthreads();
    if (threadIdx.x == 0) {
        __threadfence();
        int gen = *((volatile int*)&g_bar_gen);
        if (atomicAdd(&g_bar_count, 1) == (int)gridDim.x - 1) {
            g_bar_count = 0;
            __threadfence();
            atomicAdd(&g_bar_gen, 1);
        } else {
            while (*((volatile int*)&g_bar_gen) == gen) { __nanosleep(128); }
        }
        __threadfence();
    }
    __syncthreads();
}

// ---------------------------------------------------------------------------
// One SSIM tile (+ fused pool). H, TY compile-time. Offset space (x - 0.5).
// EDGE=false: tile fully interior -> no load/store/output bounds checks.
// ---------------------------------------------------------------------------
template <int H, int TYV, bool DO_POOL, bool SUB, bool PERSIST, bool EDGE>
__device__ __forceinline__ void ssim_tile(
    SmemWS* ws,
    const float* __restrict__ P, const float* __restrict__ T,
    int level, int out_off, int ch, int bx, int by)
{
    constexpr int W = H;
    constexpr int OH = H - 10;
    constexpr int ROWS = TYV + 10;           // input rows needed
    constexpr int OUT_PER = (TYV + 7) / 8;   // outputs per Stage-B thread
    const int t = threadIdx.x;

    const float* Pc = P + (size_t)ch * (H * W);
    const float* Tc = T + (size_t)ch * (H * W);

    ull W2[6];
#pragma unroll
    for (int i = 0; i < 6; i++) W2[i] = pk2(GW[i], GW[i]);

    // ---------------- Stage A: horizontal pass + fused pool ----------------
    {
        const int r  = t >> 2;
        const int c0 = (t & 3) * 8;
        const int gy = by + r;
        const bool rowok = (r < ROWS) && (gy < H);
        const float* rowP = Pc + (size_t)gy * W + bx + c0;
        const float* rowT = Tc + (size_t)gy * W + bx + c0;

        ull s01[8], s2[8];
        float plP[4], plT[4];
#pragma unroll
        for (int j = 0; j < 8; j++) { s01[j] = 0ULL; s2[j] = 0ULL; }

        // chunk 0 preload
        float4 pv4, tv4;
        if (EDGE) {
            pv4 = make_float4(0.f, 0.f, 0.f, 0.f);
            tv4 = make_float4(0.f, 0.f, 0.f, 0.f);
            if (rowok && (bx + c0) < W) {
                pv4 = *(const float4*)(rowP);
                tv4 = *(const float4*)(rowT);
            }
        } else {
            pv4 = *(const float4*)(rowP);
            tv4 = *(const float4*)(rowT);
        }

#pragma unroll
        for (int chk = 0; chk < 5; chk++) {
            // prefetch chunk chk+1
            float4 npv = make_float4(0.f, 0.f, 0.f, 0.f);
            float4 ntv = make_float4(0.f, 0.f, 0.f, 0.f);
            if (chk < 4) {
                if (EDGE) {
                    int ngx = bx + c0 + (chk + 1) * 4;
                    if (rowok && ngx < W) {
                        npv = *(const float4*)(rowP + (chk + 1) * 4);
                        ntv = *(const float4*)(rowT + (chk + 1) * 4);
                    }
                } else {
                    npv = *(const float4*)(rowP + (chk + 1) * 4);
                    ntv = *(const float4*)(rowT + (chk + 1) * 4);
                }
            }

            if (SUB) {
                pv4.x -= 0.5f; pv4.y -= 0.5f; pv4.z -= 0.5f; pv4.w -= 0.5f;
                tv4.x -= 0.5f; tv4.y -= 0.5f; tv4.z -= 0.5f; tv4.w -= 0.5f;
            }

            if (DO_POOL && chk < 2) {
                plP[chk * 2 + 0] = pv4.x + pv4.y;
                plP[chk * 2 + 1] = pv4.z + pv4.w;
                plT[chk * 2 + 0] = tv4.x + tv4.y;
                plT[chk * 2 + 1] = tv4.z + tv4.w;
            }

            const float pa[4] = {pv4.x, pv4.y, pv4.z, pv4.w};
            const float ta[4] = {tv4.x, tv4.y, tv4.z, tv4.w};
#pragma unroll
            for (int q = 0; q < 4; q++) {
                const int k = chk * 4 + q;
                if (k < 18) {
                    float pv = pa[q], tv = ta[q];
                    ull ptp = pk2(pv, tv);
                    float ssv = fmaf(pv, pv, tv * tv);   // p^2 + t^2
                    float ptv = pv * tv;
                    ull ssp = pk2(ssv, ptv);
#pragma unroll
                    for (int j = 0; j < 8; j++) {
                        const int i = k - j;
                        if (i >= 0 && i <= 10) {
                            FMA2(s01[j], W2AT(i), ptp, s01[j]);
                            FMA2(s2[j],  W2AT(i), ssp, s2[j]);
                        }
                    }
                }
            }

            if (DO_POOL && chk == 1) {
                float vp[4], vt[4];
#pragma unroll
                for (int q = 0; q < 4; q++) {
                    vp[q] = plP[q] + __shfl_down_sync(0xffffffffu, plP[q], 4);
                    vt[q] = plT[q] + __shfl_down_sync(0xffffffffu, plT[q], 4);
                }
                bool wr = ((r & 1) == 0) && (r + 1 < ROWS);
                if (EDGE) wr = wr && (gy + 1 < H);
                if (wr) {
                    constexpr int Ho = H >> 1;
                    size_t o = (size_t)ch * (Ho * Ho) + (size_t)(gy >> 1) * Ho
                               + ((bx + c0) >> 1);
                    *(float4*)(g_scr_p + out_off + o) =
                        make_float4(0.25f * vp[0], 0.25f * vp[1],
                                    0.25f * vp[2], 0.25f * vp[3]);
                    *(float4*)(g_scr_t + out_off + o) =
                        make_float4(0.25f * vt[0], 0.25f * vt[1],
                                    0.25f * vt[2], 0.25f * vt[3]);
                }
            }
            pv4 = npv; tv4 = ntv;
        }
        // swz(c0+j, r) = c0 | ((j + qoff) & 7), qoff = (c0>>3) + 4*(r&1)
        {
            ulonglong2* rowp = &ws->hs[r][c0];
            const int qoff = (c0 >> 3) + ((r & 1) << 2);
#pragma unroll
            for (int j = 0; j < 8; j++) {
                rowp[(j + qoff) & 7] = make_ulonglong2(s01[j], s2[j]);
            }
        }
    }
    __syncthreads();

    // ---------------- Stage B: vertical pass + SSIM ----------------
    const float C1v = 0.01f * 0.01f;
    const float C2v = 0.03f * 0.03f;
    float lsim = 0.f, lcs = 0.f;
    {
        const int tx = t & 31;
        const int g  = t >> 5;
        const int r0 = g * OUT_PER;
        const int cnt = (TYV - r0) < OUT_PER ? (TYV - r0) : OUT_PER;
        const int ox = bx + tx;

        // even/odd-row swizzled base pointers -> immediate-offset LDS
        const int pr = r0 & 1;
        const ulonglong2* pe = &ws->hs[r0][swz(tx, pr)];
        const ulonglong2* po = &ws->hs[r0 + 1][swz(tx, pr ^ 1)];

        ull a01[OUT_PER], a2[OUT_PER];
#pragma unroll
        for (int j = 0; j < OUT_PER; j++) { a01[j] = 0ULL; a2[j] = 0ULL; }

#pragma unroll
        for (int k = 0; k < OUT_PER + 10; k++) {
            ulonglong2 h = (k & 1) ? po[((k - 1) >> 1) * 64]
                                   : pe[(k >> 1) * 64];
#pragma unroll
            for (int j = 0; j < OUT_PER; j++) {
                const int i = k - j;
                if (i >= 0 && i <= 10) {
                    FMA2(a01[j], W2AT(i), h.x, a01[j]);
                    FMA2(a2[j],  W2AT(i), h.y, a2[j]);
                }
            }
        }

#pragma unroll
        for (int j = 0; j < OUT_PER; j++) {
            int oy = by + r0 + j;
            bool valid = (j < cnt);
            if (EDGE) valid = valid && (oy < OH) && (ox < OH);
            if (valid) {
                float m1o, m2o, ssq, spt;
                upk2(a01[j], m1o, m2o);
                upk2(a2[j],  ssq, spt);
                float s12 = spt - m1o * m2o;
                float v2  = ssq - m1o * m1o - m2o * m2o + C2v;
                float m1 = m1o + 0.5f, m2 = m2o + 0.5f;
                float m1s = m1 * m1, m2s = m2 * m2, m12 = m1 * m2;
                float v1 = 2.f * s12 + C2v;
                float cs  = __fdividef(v1, v2);
                float sim = cs * __fdividef(2.f * m12 + C1v, m1s + m2s + C1v);
                lcs  += cs;
                lsim += sim;
            }
        }
    }

#pragma unroll
    for (int o = 16; o > 0; o >>= 1) {
        lsim += __shfl_down_sync(0xffffffff, lsim, o);
        lcs  += __shfl_down_sync(0xffffffff, lcs, o);
    }
    if ((t & 31) == 0) { ws->rs[t >> 5] = lsim; ws->rc[t >> 5] = lcs; }
    __syncthreads();
    if (t == 0) {
        float ss = 0.f, cc = 0.f;
#pragma unroll
        for (int i = 0; i < 8; i++) { ss += ws->rs[i]; cc += ws->rc[i]; }
        atomicAdd(&g_sim_acc[level * NCH + ch], ss);
        atomicAdd(&g_cs_acc[level * NCH + ch], cc);
    }
    if (PERSIST) __syncthreads();
}

// dispatch helper: interior tiles skip all bounds checks (TY=54 only:
// smaller tiles have threads past ROWS whose loads must stay predicated)
template <int H, bool DO_POOL, bool SUB, bool PERSIST>
__device__ __forceinline__ void ssim_tile54(
    SmemWS* ws, const float* __restrict__ P, const float* __restrict__ T,
    int level, int out_off, int ch, int bx, int by)
{
    const bool interior = (bx + 48 <= H) && (by + 64 <= H);
    if (interior)
        ssim_tile<H, 54, DO_POOL, SUB, PERSIST, false>(ws, P, T, level,
                                                       out_off, ch, bx, by);
    else
        ssim_tile<H, 54, DO_POOL, SUB, PERSIST, true>(ws, P, T, level,
                                                      out_off, ch, bx, by);
}

// ---------------------------------------------------------------------------
// L0 / L1: standalone, one tile per CTA, 4 CTAs/SM target.
// ---------------------------------------------------------------------------
__global__ __launch_bounds__(256, 4)
void ssim_l0_kernel(const float* __restrict__ P, const float* __restrict__ T)
{
    __shared__ SmemWS ws;
    ssim_tile54<1024, true, true, false>(
        &ws, P, T, 0, OFF_L1, blockIdx.z, blockIdx.x * TX, blockIdx.y * 54);
}

__global__ __launch_bounds__(256, 4)
void ssim_l1_kernel()
{
    __shared__ SmemWS ws;
    ssim_tile54<512, true, false, false>(
        &ws, g_scr_p + OFF_L1, g_scr_t + OFF_L1, 1, OFF_L2,
        blockIdx.z, blockIdx.x * TX, blockIdx.y * 54);
}

// ---------------------------------------------------------------------------
// Persistent kernel: levels 2..4 with grid barriers, then fp32 combine.
// ---------------------------------------------------------------------------
template <int H, int TYV, bool DO_POOL>
__device__ __forceinline__ void run_level(SmemWS* ws, int level,
                                          int in_off, int out_off)
{
    constexpr int gx  = (H - 10 + TX - 1) / TX;
    constexpr int gyn = (H - 10 + TYV - 1) / TYV;
    constexpr int per_ch = gx * gyn;
    constexpr int tiles = per_ch * NCH;
    const float* Pl = (const float*)(g_scr_p + in_off);
    const float* Tl = (const float*)(g_scr_t + in_off);

#pragma unroll 1
    for (int w = blockIdx.x; w < tiles; w += gridDim.x) {
        int ch  = w / per_ch;
        int rem = w - ch * per_ch;
        int tyI = rem / gx;
        int txI = rem - tyI * gx;
        if (TYV == 54) {
            ssim_tile54<H, DO_POOL, false, true>(ws, Pl, Tl, level, out_off,
                                                 ch, txI * TX, tyI * TYV);
        } else {
            ssim_tile<H, TYV, DO_POOL, false, true, true>(
                ws, Pl, Tl, level, out_off, ch, txI * TX, tyI * TYV);
        }
    }
}

__global__ __launch_bounds__(256, 3)
void ssim_rest_kernel(float* __restrict__ out)
{
    __shared__ SmemWS ws;

    run_level<256, 54, true >(&ws, 2, OFF_L2, OFF_L3);   // 400 tiles
    grid_barrier();
    run_level<128, 28, true >(&ws, 3, OFF_L3, OFF_L4);   // 200 tiles
    grid_barrier();
    run_level<64,  14, false>(&ws, 4, OFF_L4, 0);        // 80 tiles
    grid_barrier();

    // fp32 combine: thread c (<10) handles category c.
    if (blockIdx.x == 0) {
        __shared__ float part[NCH];
        const int t = threadIdx.x;
        if (t < NCH) {
            const float w[5]    = {0.0448f, 0.2856f, 0.3001f, 0.2363f, 0.1333f};
            const float icnt[5] = {1.f / (1014.f * 1014.f), 1.f / (502.f * 502.f),
                                   1.f / (246.f * 246.f),  1.f / (118.f * 118.f),
                                   1.f / (54.f * 54.f)};
            float ms4 = g_sim_acc[4 * NCH + t] * icnt[4];
            float e = 4.0f * w[4] * log2f(ms4);
            for (int l = 0; l < 4; l++) {
                float mc = g_cs_acc[l * NCH + t] * icnt[l];
                e += w[l] * log2f(mc);
            }
            part[t] = exp2f(e);
        }
        __syncthreads();
        if (t == 0) {
            float total = 0.f;
            for (int c = 0; c < NCH; c++) total += part[c];
            out[0] = 1.0f - total;
        }
        if (t < 50) { g_sim_acc[t] = 0.f; g_cs_acc[t] = 0.f; }
    }
}

extern "C" void kernel_launch(void* const* d_in, const int* in_sizes, int n_in,
                              void* d_out, int out_size)
{
    const float* P = (const float*)d_in[0];
    const float* T = (const float*)d_in[1];
    float* out = (float*)d_out;

    dim3 grid0(32, 19, NCH);   // L0: 1024 -> OH 1014
    ssim_l0_kernel<<<grid0, 256>>>(P, T);
    dim3 grid1(16, 10, NCH);   // L1: 512 -> OH 502
    ssim_l1_kernel<<<grid1, 256>>>();
    ssim_rest_kernel<<<NBLK2, 256>>>(out);
}

// round 15
// speedup vs baseline: 3.4870x; 1.0532x over previous
#include <cuda_runtime.h>
#include <math.h>

// ---------------------------------------------------------------------------
// MS-SSIM loss. 10 channels 1024x1024 fp32, 5 levels.
// Key algebra: reference uses prod(pow1[:-1] * pow2[-1]) -> only CS from
// levels 0-3 and only SIM from level 4 matter. Each level computes just the
// one quantity it contributes (NEED_SIM flag), cutting the per-pixel
// epilogue ~2x on the three dominant kernels.
// L0, L1: standalone @ 4 CTAs/SM, interior-tile specialization.
// L2-L4 + combine: persistent kernel with grid barriers. fp32 combine.
// ---------------------------------------------------------------------------

#define NCH 10
#define TX 32
#define NBLK2 400

__device__ constexpr float GW[11] = {
    0.00102842f, 0.00759877f, 0.03600077f, 0.10936076f, 0.21300535f,
    0.26601172f,
    0.21300535f, 0.10936076f, 0.03600077f, 0.00759877f, 0.00102842f};

__device__ float g_sim_acc[50];   // [level][channel] (only level 4 used)
__device__ float g_cs_acc[50];    // (only levels 0-3 used)
__device__ int g_bar_count;
__device__ int g_bar_gen;

#define SCR_TOTAL 3481600
__device__ __align__(16) float g_scr_p[SCR_TOTAL];
__device__ __align__(16) float g_scr_t[SCR_TOTAL];

#define OFF_L1 0
#define OFF_L2 2621440
#define OFF_L3 3276800
#define OFF_L4 3440640

// shared workspace sized for the largest tile (TY=54 -> 64 rows + 2 spare)
struct SmemWS {
    ulonglong2 hs[66][32];   // (s01, s2) packed pairs, bank-swizzled columns
    float rs[8];
};

__device__ __forceinline__ int swz(int col, int row) {
    return (col & 24) | (((col & 7) + ((col >> 3) & 3) + ((row & 1) << 2)) & 7);
}

// ---- f32x2 packed math helpers --------------------------------------------
typedef unsigned long long ull;

__device__ __forceinline__ ull pk2(float a, float b) {
    ull r; asm("mov.b64 %0, {%1, %2};" : "=l"(r) : "f"(a), "f"(b)); return r;
}
__device__ __forceinline__ void upk2(ull v, float& a, float& b) {
    asm("mov.b64 {%0, %1}, %2;" : "=f"(a), "=f"(b) : "l"(v));
}
#define FMA2(d, a, b, c) \
    asm("fma.rn.f32x2 %0, %1, %2, %3;" : "=l"(d) : "l"(a), "l"(b), "l"(c))
#define W2AT(i) W2[(i) < 6 ? (i) : 10 - (i)]

__device__ __forceinline__ void grid_barrier()
{
    __syncthreads();
    if (threadIdx.x == 0) {
        __threadfence();
        int gen = *((volatile int*)&g_bar_gen);
        if (atomicAdd(&g_bar_count, 1) == (int)gridDim.x - 1) {
            g_bar_count = 0;
            __threadfence();
            atomicAdd(&g_bar_gen, 1);
        } else {
            while (*((volatile int*)&g_bar_gen) == gen) { __nanosleep(128); }
        }
        __threadfence();
    }
    __syncthreads();
}

// ---------------------------------------------------------------------------
// One SSIM tile (+ fused pool). H, TY compile-time. Offset space (x - 0.5).
// EDGE=false: interior tile, no bounds checks. NEED_SIM: level-4 path
// (accumulate sim); otherwise accumulate cs only.
// ---------------------------------------------------------------------------
template <int H, int TYV, bool DO_POOL, bool SUB, bool PERSIST, bool EDGE,
          bool NEED_SIM>
__device__ __forceinline__ void ssim_tile(
    SmemWS* ws,
    const float* __restrict__ P, const float* __restrict__ T,
    int level, int out_off, int ch, int bx, int by)
{
    constexpr int W = H;
    constexpr int OH = H - 10;
    constexpr int ROWS = TYV + 10;
    constexpr int OUT_PER = (TYV + 7) / 8;
    const int t = threadIdx.x;

    const float* Pc = P + (size_t)ch * (H * W);
    const float* Tc = T + (size_t)ch * (H * W);

    ull W2[6];
#pragma unroll
    for (int i = 0; i < 6; i++) W2[i] = pk2(GW[i], GW[i]);

    // ---------------- Stage A: horizontal pass + fused pool ----------------
    {
        const int r  = t >> 2;
        const int c0 = (t & 3) * 8;
        const int gy = by + r;
        const bool rowok = (r < ROWS) && (gy < H);
        const float* rowP = Pc + (size_t)gy * W + bx + c0;
        const float* rowT = Tc + (size_t)gy * W + bx + c0;

        ull s01[8], s2[8];
        float plP[4], plT[4];
#pragma unroll
        for (int j = 0; j < 8; j++) { s01[j] = 0ULL; s2[j] = 0ULL; }

        float4 pv4, tv4;
        if (EDGE) {
            pv4 = make_float4(0.f, 0.f, 0.f, 0.f);
            tv4 = make_float4(0.f, 0.f, 0.f, 0.f);
            if (rowok && (bx + c0) < W) {
                pv4 = *(const float4*)(rowP);
                tv4 = *(const float4*)(rowT);
            }
        } else {
            pv4 = *(const float4*)(rowP);
            tv4 = *(const float4*)(rowT);
        }

#pragma unroll
        for (int chk = 0; chk < 5; chk++) {
            float4 npv = make_float4(0.f, 0.f, 0.f, 0.f);
            float4 ntv = make_float4(0.f, 0.f, 0.f, 0.f);
            if (chk < 4) {
                if (EDGE) {
                    int ngx = bx + c0 + (chk + 1) * 4;
                    if (rowok && ngx < W) {
                        npv = *(const float4*)(rowP + (chk + 1) * 4);
                        ntv = *(const float4*)(rowT + (chk + 1) * 4);
                    }
                } else {
                    npv = *(const float4*)(rowP + (chk + 1) * 4);
                    ntv = *(const float4*)(rowT + (chk + 1) * 4);
                }
            }

            if (SUB) {
                pv4.x -= 0.5f; pv4.y -= 0.5f; pv4.z -= 0.5f; pv4.w -= 0.5f;
                tv4.x -= 0.5f; tv4.y -= 0.5f; tv4.z -= 0.5f; tv4.w -= 0.5f;
            }

            if (DO_POOL && chk < 2) {
                plP[chk * 2 + 0] = pv4.x + pv4.y;
                plP[chk * 2 + 1] = pv4.z + pv4.w;
                plT[chk * 2 + 0] = tv4.x + tv4.y;
                plT[chk * 2 + 1] = tv4.z + tv4.w;
            }

            const float pa[4] = {pv4.x, pv4.y, pv4.z, pv4.w};
            const float ta[4] = {tv4.x, tv4.y, tv4.z, tv4.w};
#pragma unroll
            for (int q = 0; q < 4; q++) {
                const int k = chk * 4 + q;
                if (k < 18) {
                    float pv = pa[q], tv = ta[q];
                    ull ptp = pk2(pv, tv);
                    float ssv = fmaf(pv, pv, tv * tv);   // p^2 + t^2
                    float ptv = pv * tv;
                    ull ssp = pk2(ssv, ptv);
#pragma unroll
                    for (int j = 0; j < 8; j++) {
                        const int i = k - j;
                        if (i >= 0 && i <= 10) {
                            FMA2(s01[j], W2AT(i), ptp, s01[j]);
                            FMA2(s2[j],  W2AT(i), ssp, s2[j]);
                        }
                    }
                }
            }

            if (DO_POOL && chk == 1) {
                float vp[4], vt[4];
#pragma unroll
                for (int q = 0; q < 4; q++) {
                    vp[q] = plP[q] + __shfl_down_sync(0xffffffffu, plP[q], 4);
                    vt[q] = plT[q] + __shfl_down_sync(0xffffffffu, plT[q], 4);
                }
                bool wr = ((r & 1) == 0) && (r + 1 < ROWS);
                if (EDGE) wr = wr && (gy + 1 < H);
                if (wr) {
                    constexpr int Ho = H >> 1;
                    size_t o = (size_t)ch * (Ho * Ho) + (size_t)(gy >> 1) * Ho
                               + ((bx + c0) >> 1);
                    *(float4*)(g_scr_p + out_off + o) =
                        make_float4(0.25f * vp[0], 0.25f * vp[1],
                                    0.25f * vp[2], 0.25f * vp[3]);
                    *(float4*)(g_scr_t + out_off + o) =
                        make_float4(0.25f * vt[0], 0.25f * vt[1],
                                    0.25f * vt[2], 0.25f * vt[3]);
                }
            }
            pv4 = npv; tv4 = ntv;
        }
        // swz(c0+j, r) = c0 | ((j + qoff) & 7), qoff = (c0>>3) + 4*(r&1)
        {
            ulonglong2* rowp = &ws->hs[r][c0];
            const int qoff = (c0 >> 3) + ((r & 1) << 2);
#pragma unroll
            for (int j = 0; j < 8; j++) {
                rowp[(j + qoff) & 7] = make_ulonglong2(s01[j], s2[j]);
            }
        }
    }
    __syncthreads();

    // ---------------- Stage B: vertical pass + SSIM ----------------
    const float C1v = 0.01f * 0.01f;
    const float C2v = 0.03f * 0.03f;
    float lacc = 0.f;     // cs-sum (levels 0-3) or sim-sum (level 4)
    {
        const int tx = t & 31;
        const int g  = t >> 5;
        const int r0 = g * OUT_PER;
        const int cnt = (TYV - r0) < OUT_PER ? (TYV - r0) : OUT_PER;
        const int ox = bx + tx;

        const int pr = r0 & 1;
        const ulonglong2* pe = &ws->hs[r0][swz(tx, pr)];
        const ulonglong2* po = &ws->hs[r0 + 1][swz(tx, pr ^ 1)];

        ull a01[OUT_PER], a2[OUT_PER];
#pragma unroll
        for (int j = 0; j < OUT_PER; j++) { a01[j] = 0ULL; a2[j] = 0ULL; }

#pragma unroll
        for (int k = 0; k < OUT_PER + 10; k++) {
            ulonglong2 h = (k & 1) ? po[((k - 1) >> 1) * 64]
                                   : pe[(k >> 1) * 64];
#pragma unroll
            for (int j = 0; j < OUT_PER; j++) {
                const int i = k - j;
                if (i >= 0 && i <= 10) {
                    FMA2(a01[j], W2AT(i), h.x, a01[j]);
                    FMA2(a2[j],  W2AT(i), h.y, a2[j]);
                }
            }
        }

#pragma unroll
        for (int j = 0; j < OUT_PER; j++) {
            int oy = by + r0 + j;
            bool valid = (j < cnt);
            if (EDGE) valid = valid && (oy < OH) && (ox < OH);
            if (valid) {
                float m1o, m2o, ssq, spt;
                upk2(a01[j], m1o, m2o);
                upk2(a2[j],  ssq, spt);
                float s12 = spt - m1o * m2o;
                float v2  = ssq - m1o * m1o - m2o * m2o + C2v;
                float v1 = 2.f * s12 + C2v;
                float cs = __fdividef(v1, v2);
                if (NEED_SIM) {
                    float m1 = m1o + 0.5f, m2 = m2o + 0.5f;
                    float m12 = m1 * m2;
                    float lum = __fdividef(2.f * m12 + C1v,
                                           fmaf(m1, m1, m2 * m2) + C1v);
                    lacc += cs * lum;
                } else {
                    lacc += cs;
                }
            }
        }
    }

#pragma unroll
    for (int o = 16; o > 0; o >>= 1)
        lacc += __shfl_down_sync(0xffffffff, lacc, o);
    if ((t & 31) == 0) ws->rs[t >> 5] = lacc;
    __syncthreads();
    if (t == 0) {
        float ss = 0.f;
#pragma unroll
        for (int i = 0; i < 8; i++) ss += ws->rs[i];
        float* dst = NEED_SIM ? g_sim_acc : g_cs_acc;
        atomicAdd(&dst[level * NCH + ch], ss);
    }
    if (PERSIST) __syncthreads();
}

// dispatch helper: interior tiles skip all bounds checks (TY=54 only)
template <int H, bool DO_POOL, bool SUB, bool PERSIST>
__device__ __forceinline__ void ssim_tile54(
    SmemWS* ws, const float* __restrict__ P, const float* __restrict__ T,
    int level, int out_off, int ch, int bx, int by)
{
    const bool interior = (bx + 48 <= H) && (by + 64 <= H);
    if (interior)
        ssim_tile<H, 54, DO_POOL, SUB, PERSIST, false, false>(
            ws, P, T, level, out_off, ch, bx, by);
    else
        ssim_tile<H, 54, DO_POOL, SUB, PERSIST, true, false>(
            ws, P, T, level, out_off, ch, bx, by);
}

// ---------------------------------------------------------------------------
// L0 / L1: standalone, one tile per CTA, 4 CTAs/SM target.
// ---------------------------------------------------------------------------
__global__ __launch_bounds__(256, 4)
void ssim_l0_kernel(const float* __restrict__ P, const float* __restrict__ T)
{
    __shared__ SmemWS ws;
    ssim_tile54<1024, true, true, false>(
        &ws, P, T, 0, OFF_L1, blockIdx.z, blockIdx.x * TX, blockIdx.y * 54);
}

__global__ __launch_bounds__(256, 4)
void ssim_l1_kernel()
{
    __shared__ SmemWS ws;
    ssim_tile54<512, true, false, false>(
        &ws, g_scr_p + OFF_L1, g_scr_t + OFF_L1, 1, OFF_L2,
        blockIdx.z, blockIdx.x * TX, blockIdx.y * 54);
}

// ---------------------------------------------------------------------------
// Persistent kernel: levels 2..4 with grid barriers, then fp32 combine.
// ---------------------------------------------------------------------------
template <int H, int TYV, bool DO_POOL, bool NEED_SIM>
__device__ __forceinline__ void run_level(SmemWS* ws, int level,
                                          int in_off, int out_off)
{
    constexpr int gx  = (H - 10 + TX - 1) / TX;
    constexpr int gyn = (H - 10 + TYV - 1) / TYV;
    constexpr int per_ch = gx * gyn;
    constexpr int tiles = per_ch * NCH;
    const float* Pl = (const float*)(g_scr_p + in_off);
    const float* Tl = (const float*)(g_scr_t + in_off);

#pragma unroll 1
    for (int w = blockIdx.x; w < tiles; w += gridDim.x) {
        int ch  = w / per_ch;
        int rem = w - ch * per_ch;
        int tyI = rem / gx;
        int txI = rem - tyI * gx;
        if (TYV == 54 && !NEED_SIM) {
            ssim_tile54<H, DO_POOL, false, true>(ws, Pl, Tl, level, out_off,
                                                 ch, txI * TX, tyI * TYV);
        } else {
            ssim_tile<H, TYV, DO_POOL, false, true, true, NEED_SIM>(
                ws, Pl, Tl, level, out_off, ch, txI * TX, tyI * TYV);
        }
    }
}

__global__ __launch_bounds__(256, 3)
void ssim_rest_kernel(float* __restrict__ out)
{
    __shared__ SmemWS ws;

    run_level<256, 54, true,  false>(&ws, 2, OFF_L2, OFF_L3);   // 400 tiles
    grid_barrier();
    run_level<128, 28, true,  false>(&ws, 3, OFF_L3, OFF_L4);   // 200 tiles
    grid_barrier();
    run_level<64,  14, false, true >(&ws, 4, OFF_L4, 0);        // 80 tiles
    grid_barrier();

    // fp32 combine: thread c (<10) handles category c.
    if (blockIdx.x == 0) {
        __shared__ float part[NCH];
        const int t = threadIdx.x;
        if (t < NCH) {
            const float w[5]    = {0.0448f, 0.2856f, 0.3001f, 0.2363f, 0.1333f};
            const float icnt[5] = {1.f / (1014.f * 1014.f), 1.f / (502.f * 502.f),
                                   1.f / (246.f * 246.f),  1.f / (118.f * 118.f),
                                   1.f / (54.f * 54.f)};
            float ms4 = g_sim_acc[4 * NCH + t] * icnt[4];
            float e = 4.0f * w[4] * log2f(ms4);
            for (int l = 0; l < 4; l++) {
                float mc = g_cs_acc[l * NCH + t] * icnt[l];
                e += w[l] * log2f(mc);
            }
            part[t] = exp2f(e);
        }
        __syncthreads();
        if (t == 0) {
            float total = 0.f;
            for (int c = 0; c < NCH; c++) total += part[c];
            out[0] = 1.0f - total;
        }
        if (t < 50) { g_sim_acc[t] = 0.f; g_cs_acc[t] = 0.f; }
    }
}

extern "C" void kernel_launch(void* const* d_in, const int* in_sizes, int n_in,
                              void* d_out, int out_size)
{
    const float* P = (const float*)d_in[0];
    const float* T = (const float*)d_in[1];
    float* out = (float*)d_out;

    dim3 grid0(32, 19, NCH);   // L0: 1024 -> OH 1014
    ssim_l0_kernel<<<grid0, 256>>>(P, T);
    dim3 grid1(16, 10, NCH);   // L1: 512 -> OH 502
    ssim_l1_kernel<<<grid1, 256>>>();
    ssim_rest_kernel<<<NBLK2, 256>>>(out);
}